// round 3
// baseline (speedup 1.0000x reference)
#include <cuda_runtime.h>
#include <math.h>
#include <stdint.h>

#define BATCH 4
#define SEQ   2048
#define DIM   1024
#define NH    16
#define HD    64
#define MTOK  (BATCH*SEQ)        // 8192
#define SCALE 0.125f             // 1/sqrt(64)

// Scratch (allocation-free: __device__ globals)
__device__ float g_q[BATCH*NH*SEQ*HD];     // 32 MB
__device__ float g_k[BATCH*NH*SEQ*HD];     // 32 MB
__device__ float g_v[BATCH*NH*SEQ*HD];     // 32 MB
__device__ float g_attn[MTOK*DIM];         // 32 MB

// ---------------------------------------------------------------------------
// tf32 helpers
// ---------------------------------------------------------------------------
__device__ __forceinline__ uint32_t tf32cvt(float x) {
    uint32_t r;
    asm("cvt.rna.tf32.f32 %0, %1;" : "=r"(r) : "f"(x));
    return r;
}

__device__ __forceinline__ void mma_tf32(float c[4],
                                         const uint32_t a[4],
                                         const uint32_t b[2]) {
    asm volatile(
        "mma.sync.aligned.m16n8k8.row.col.f32.tf32.tf32.f32 "
        "{%0,%1,%2,%3},{%4,%5,%6,%7},{%8,%9},{%0,%1,%2,%3};"
        : "+f"(c[0]), "+f"(c[1]), "+f"(c[2]), "+f"(c[3])
        : "r"(a[0]), "r"(a[1]), "r"(a[2]), "r"(a[3]),
          "r"(b[0]), "r"(b[1]));
}

// ---------------------------------------------------------------------------
// tf32 MMA GEMM: 128x128 block tile, BK=16, 256 threads = 8 warps (2x4),
// warp tile 64x32. SMEM holds tf32-converted operands, k-major, pitch 136
// (136 mod 32 == 8 -> fragment LDS are conflict-free). Double-buffered.
// ---------------------------------------------------------------------------
#define GBM 128
#define GBN 128
#define GBK 16
#define KP  136

__device__ __forceinline__ void sts_a(uint32_t (*As)[KP], int rA, int cgA,
                                      float4 a0, float4 a1) {
    As[cgA+0][rA] = tf32cvt(a0.x);
    As[cgA+1][rA] = tf32cvt(a0.y);
    As[cgA+2][rA] = tf32cvt(a0.z);
    As[cgA+3][rA] = tf32cvt(a0.w);
    As[cgA+4][rA] = tf32cvt(a1.x);
    As[cgA+5][rA] = tf32cvt(a1.y);
    As[cgA+6][rA] = tf32cvt(a1.z);
    As[cgA+7][rA] = tf32cvt(a1.w);
}

__device__ __forceinline__ void sts_b(uint32_t (*Bs)[KP], int rB, int cB,
                                      float4 b0, float4 b1) {
    uint4 u;
    u.x = tf32cvt(b0.x); u.y = tf32cvt(b0.y);
    u.z = tf32cvt(b0.z); u.w = tf32cvt(b0.w);
    *(uint4*)&Bs[rB][cB] = u;
    u.x = tf32cvt(b1.x); u.y = tf32cvt(b1.y);
    u.z = tf32cvt(b1.z); u.w = tf32cvt(b1.w);
    *(uint4*)&Bs[rB][cB+4] = u;
}

__device__ __forceinline__ void gemm_compute(const uint32_t (*As)[KP],
                                             const uint32_t (*Bs)[KP],
                                             int wr, int wc, int gid, int q4,
                                             float acc[4][4][4]) {
    #pragma unroll
    for (int ks = 0; ks < 2; ks++) {
        int kb = ks * 8;
        int k  = kb + q4;
        uint32_t af[4][4], bf[4][2];
        #pragma unroll
        for (int mt = 0; mt < 4; mt++) {
            int m = wr*64 + mt*16 + gid;
            af[mt][0] = As[k][m];
            af[mt][1] = As[k][m+8];
            af[mt][2] = As[k+4][m];
            af[mt][3] = As[k+4][m+8];
        }
        #pragma unroll
        for (int nt = 0; nt < 4; nt++) {
            int n = wc*32 + nt*8 + gid;
            bf[nt][0] = Bs[k][n];
            bf[nt][1] = Bs[k+4][n];
        }
        #pragma unroll
        for (int mt = 0; mt < 4; mt++)
            #pragma unroll
            for (int nt = 0; nt < 4; nt++)
                mma_tf32(acc[mt][nt], af[mt], bf[nt]);
    }
}

// common mainloop (double-buffered) as a macro so the epilogue can differ
#define GEMM_MAIN(A_, B_, K_, N_)                                              \
    __shared__ uint32_t As[2][GBK][KP];                                        \
    __shared__ uint32_t Bs[2][GBK][KP];                                        \
    int tid  = threadIdx.x;                                                    \
    int lane = tid & 31;                                                       \
    int wid  = tid >> 5;                                                       \
    int wr = wid >> 2, wc = wid & 3, gid = lane >> 2, q4 = lane & 3;           \
    int row0 = blockIdx.y * GBM, col0 = blockIdx.x * GBN;                      \
    int rA = tid >> 1,  cgA = (tid & 1) * 8;                                   \
    int rB = tid >> 4,  cB  = (tid & 15) * 8;                                  \
    float acc[4][4][4];                                                        \
    _Pragma("unroll")                                                          \
    for (int mt = 0; mt < 4; mt++)                                             \
        _Pragma("unroll")                                                      \
        for (int nt = 0; nt < 4; nt++)                                         \
            _Pragma("unroll")                                                  \
            for (int e = 0; e < 4; e++) acc[mt][nt][e] = 0.f;                  \
    const float* aRowPtr = (A_) + (size_t)(row0 + rA) * (K_);                  \
    float4 a4[2], b4[2];                                                       \
    a4[0] = *(const float4*)&aRowPtr[cgA];                                     \
    a4[1] = *(const float4*)&aRowPtr[cgA + 4];                                 \
    b4[0] = *(const float4*)&(B_)[(size_t)rB * (N_) + col0 + cB];              \
    b4[1] = *(const float4*)&(B_)[(size_t)rB * (N_) + col0 + cB + 4];          \
    sts_a(As[0], rA, cgA, a4[0], a4[1]);                                       \
    sts_b(Bs[0], rB, cB,  b4[0], b4[1]);                                       \
    __syncthreads();                                                           \
    int buf = 0;                                                               \
    for (int k0 = GBK; ; k0 += GBK) {                                          \
        bool more = (k0 < (K_));                                               \
        if (more) {                                                            \
            a4[0] = *(const float4*)&aRowPtr[k0 + cgA];                        \
            a4[1] = *(const float4*)&aRowPtr[k0 + cgA + 4];                    \
            b4[0] = *(const float4*)&(B_)[(size_t)(k0 + rB)*(N_) + col0 + cB]; \
            b4[1] = *(const float4*)&(B_)[(size_t)(k0 + rB)*(N_) + col0 + cB + 4]; \
        }                                                                      \
        gemm_compute(As[buf], Bs[buf], wr, wc, gid, q4, acc);                  \
        if (!more) break;                                                      \
        sts_a(As[buf^1], rA, cgA, a4[0], a4[1]);                               \
        sts_b(Bs[buf^1], rB, cB,  b4[0], b4[1]);                               \
        __syncthreads();                                                       \
        buf ^= 1;                                                              \
    }

// QKV projection: C = x @ w_qkv + b_qkv, scattered into g_q/g_k/g_v (B,H,S,Hd)
__global__ void __launch_bounds__(256) mma_qkv(
    const float* __restrict__ A, const float* __restrict__ Bm,
    const float* __restrict__ bias)
{
    GEMM_MAIN(A, Bm, DIM, 3*DIM)

    #pragma unroll
    for (int mt = 0; mt < 4; mt++) {
        #pragma unroll
        for (int nt = 0; nt < 4; nt++) {
            #pragma unroll
            for (int e = 0; e < 4; e++) {
                int row = row0 + wr*64 + mt*16 + gid + (e >> 1) * 8;
                int col = col0 + wc*32 + nt*8 + 2*q4 + (e & 1);
                float v = acc[mt][nt][e] + bias[col];
                int b  = row >> 11;
                int s  = row & 2047;
                int three = col >> 10;
                int rem   = col & 1023;
                int h     = rem >> 6;
                int hd    = rem & 63;
                size_t dst = ((size_t)(b*NH + h)*SEQ + s)*HD + hd;
                if (three == 0)      g_q[dst] = v;
                else if (three == 1) g_k[dst] = v;
                else                 g_v[dst] = v;
            }
        }
    }
}

// Output projection: d_out = g_attn @ w_out + b_out
__global__ void __launch_bounds__(256) mma_out(
    const float* __restrict__ Bm, const float* __restrict__ bias,
    float* __restrict__ C)
{
    const float* A = g_attn;
    GEMM_MAIN(A, Bm, DIM, DIM)

    #pragma unroll
    for (int mt = 0; mt < 4; mt++) {
        #pragma unroll
        for (int nt = 0; nt < 4; nt++) {
            #pragma unroll
            for (int e = 0; e < 4; e++) {
                int row = row0 + wr*64 + mt*16 + gid + (e >> 1) * 8;
                int col = col0 + wc*32 + nt*8 + 2*q4 + (e & 1);
                C[(size_t)row*DIM + col] = acc[mt][nt][e] + bias[col];
            }
        }
    }
}

// ---------------------------------------------------------------------------
// Fused flash attention with tf32 mma. Block = 64 queries of one (b,h),
// 128 threads = 4 warps; warp w owns q-rows [w*16, w*16+16).
// SMEM operands pre-converted to tf32, pitch 72 (== 8 mod 32) so every
// fragment LDS is conflict-free. Q and K stored d-major (transposed);
// V natural; P stored key-major (transposed). Q fragments hoisted.
// ---------------------------------------------------------------------------
#define QT 64
#define KT 64
#define FP 72

__global__ void __launch_bounds__(128) attn_kernel()
{
    extern __shared__ uint32_t smu[];
    uint32_t (*Qt)[FP] = (uint32_t (*)[FP])smu;             // [64 d][q]
    uint32_t (*Kt)[FP] = (uint32_t (*)[FP])(smu + 64*FP);   // [64 d][key]
    uint32_t (*Vs)[FP] = (uint32_t (*)[FP])(smu + 128*FP);  // [64 key][d]
    uint32_t (*Pt)[FP] = (uint32_t (*)[FP])(smu + 192*FP);  // [64 key][q]

    int tid  = threadIdx.x;
    int lane = tid & 31;
    int w    = tid >> 5;     // 0..3
    int gid  = lane >> 2;    // 0..7
    int q4   = lane & 3;     // 0..3
    int m    = w*16 + gid;   // warp-local a-fragment row

    int b  = blockIdx.z;
    int h  = blockIdx.y;
    int q0 = blockIdx.x * QT;

    const float* qptr = g_q + ((size_t)(b*NH + h)*SEQ)*HD;
    const float* kptr = g_k + ((size_t)(b*NH + h)*SEQ)*HD;
    const float* vptr = g_v + ((size_t)(b*NH + h)*SEQ)*HD;

    // load Q tile transposed + scaled + tf32
    #pragma unroll
    for (int it = 0; it < 8; it++) {
        int e  = tid + it*128;
        int r  = e >> 4;
        int c4 = (e & 15) * 4;
        float4 v = *(const float4*)&qptr[(size_t)(q0 + r)*HD + c4];
        Qt[c4+0][r] = tf32cvt(v.x * SCALE);
        Qt[c4+1][r] = tf32cvt(v.y * SCALE);
        Qt[c4+2][r] = tf32cvt(v.z * SCALE);
        Qt[c4+3][r] = tf32cvt(v.w * SCALE);
    }
    __syncthreads();

    // hoist Q fragments (loop-invariant over key tiles)
    uint32_t qf[8][4];
    #pragma unroll
    for (int kk = 0; kk < 8; kk++) {
        int d = kk*8 + q4;
        qf[kk][0] = Qt[d][m];
        qf[kk][1] = Qt[d][m+8];
        qf[kk][2] = Qt[d+4][m];
        qf[kk][3] = Qt[d+4][m+8];
    }

    float m_a = -INFINITY, m_b = -INFINITY;
    float l_a = 0.f, l_b = 0.f;
    float O[8][4];
    #pragma unroll
    for (int dt = 0; dt < 8; dt++)
        #pragma unroll
        for (int e = 0; e < 4; e++) O[dt][e] = 0.f;

    for (int kt = 0; kt < SEQ; kt += KT) {
        // load K (transposed) and V (natural), tf32-converted
        #pragma unroll
        for (int it = 0; it < 8; it++) {
            int e  = tid + it*128;
            int r  = e >> 4;
            int c4 = (e & 15) * 4;
            float4 kv = *(const float4*)&kptr[(size_t)(kt + r)*HD + c4];
            Kt[c4+0][r] = tf32cvt(kv.x);
            Kt[c4+1][r] = tf32cvt(kv.y);
            Kt[c4+2][r] = tf32cvt(kv.z);
            Kt[c4+3][r] = tf32cvt(kv.w);
            float4 vv = *(const float4*)&vptr[(size_t)(kt + r)*HD + c4];
            uint4 u;
            u.x = tf32cvt(vv.x); u.y = tf32cvt(vv.y);
            u.z = tf32cvt(vv.z); u.w = tf32cvt(vv.w);
            *(uint4*)&Vs[r][c4] = u;
        }
        __syncthreads();

        // S = Q @ K^T   (warp: 16 rows x 64 keys -> 8 n-tiles)
        float S[8][4];
        #pragma unroll
        for (int nt = 0; nt < 8; nt++)
            #pragma unroll
            for (int e = 0; e < 4; e++) S[nt][e] = 0.f;

        #pragma unroll
        for (int kk = 0; kk < 8; kk++) {
            int d = kk*8 + q4;
            uint32_t bf[8][2];
            #pragma unroll
            for (int nt = 0; nt < 8; nt++) {
                bf[nt][0] = Kt[d][nt*8 + gid];
                bf[nt][1] = Kt[d+4][nt*8 + gid];
            }
            #pragma unroll
            for (int nt = 0; nt < 8; nt++)
                mma_tf32(S[nt], qf[kk], bf[nt]);
        }

        // online softmax (thread owns warp-local rows gid and gid+8)
        {
            float ma = S[0][0], mb = S[0][2];
            #pragma unroll
            for (int nt = 0; nt < 8; nt++) {
                ma = fmaxf(ma, fmaxf(S[nt][0], S[nt][1]));
                mb = fmaxf(mb, fmaxf(S[nt][2], S[nt][3]));
            }
            #pragma unroll
            for (int off = 1; off <= 2; off <<= 1) {
                ma = fmaxf(ma, __shfl_xor_sync(0xffffffffu, ma, off));
                mb = fmaxf(mb, __shfl_xor_sync(0xffffffffu, mb, off));
            }
            float mna = fmaxf(m_a, ma);
            float mnb = fmaxf(m_b, mb);
            float alpha_a = __expf(m_a - mna);
            float alpha_b = __expf(m_b - mnb);
            float sa = 0.f, sb = 0.f;
            #pragma unroll
            for (int nt = 0; nt < 8; nt++) {
                S[nt][0] = __expf(S[nt][0] - mna);
                S[nt][1] = __expf(S[nt][1] - mna);
                S[nt][2] = __expf(S[nt][2] - mnb);
                S[nt][3] = __expf(S[nt][3] - mnb);
                sa += S[nt][0] + S[nt][1];
                sb += S[nt][2] + S[nt][3];
            }
            #pragma unroll
            for (int off = 1; off <= 2; off <<= 1) {
                sa += __shfl_xor_sync(0xffffffffu, sa, off);
                sb += __shfl_xor_sync(0xffffffffu, sb, off);
            }
            l_a = l_a * alpha_a + sa;
            l_b = l_b * alpha_b + sb;
            m_a = mna; m_b = mnb;
            #pragma unroll
            for (int dt = 0; dt < 8; dt++) {
                O[dt][0] *= alpha_a; O[dt][1] *= alpha_a;
                O[dt][2] *= alpha_b; O[dt][3] *= alpha_b;
            }
        }

        // stage P (transposed: key-major) into warp-private columns
        #pragma unroll
        for (int nt = 0; nt < 8; nt++) {
            int col = nt*8 + 2*q4;
            Pt[col][m]       = tf32cvt(S[nt][0]);
            Pt[col+1][m]     = tf32cvt(S[nt][1]);
            Pt[col][m+8]     = tf32cvt(S[nt][2]);
            Pt[col+1][m+8]   = tf32cvt(S[nt][3]);
        }
        __syncwarp();

        // O += P @ V
        #pragma unroll
        for (int kk = 0; kk < 8; kk++) {
            int kkey = kk*8 + q4;
            uint32_t af[4];
            af[0] = Pt[kkey][m];
            af[1] = Pt[kkey][m+8];
            af[2] = Pt[kkey+4][m];
            af[3] = Pt[kkey+4][m+8];
            uint32_t bf[8][2];
            #pragma unroll
            for (int dt = 0; dt < 8; dt++) {
                bf[dt][0] = Vs[kkey][dt*8 + gid];
                bf[dt][1] = Vs[kkey+4][dt*8 + gid];
            }
            #pragma unroll
            for (int dt = 0; dt < 8; dt++)
                mma_tf32(O[dt], af, bf[dt]);
        }
        __syncthreads();   // before next tile overwrites Kt/Vs
    }

    // write normalized output in (B,S,D) layout for the final GEMM
    float inv_a = 1.f / l_a;
    float inv_b = 1.f / l_b;
    size_t rowbase_a = ((size_t)b*SEQ + q0 + m)*DIM + h*HD;
    size_t rowbase_b = ((size_t)b*SEQ + q0 + m + 8)*DIM + h*HD;
    #pragma unroll
    for (int dt = 0; dt < 8; dt++) {
        int col = dt*8 + 2*q4;
        g_attn[rowbase_a + col]     = O[dt][0] * inv_a;
        g_attn[rowbase_a + col + 1] = O[dt][1] * inv_a;
        g_attn[rowbase_b + col]     = O[dt][2] * inv_b;
        g_attn[rowbase_b + col + 1] = O[dt][3] * inv_b;
    }
}

// ---------------------------------------------------------------------------
extern "C" void kernel_launch(void* const* d_in, const int* in_sizes, int n_in,
                              void* d_out, int out_size)
{
    const float* x      = (const float*)d_in[0];
    const float* w_qkv  = (const float*)d_in[1];
    const float* b_qkv  = (const float*)d_in[2];
    const float* w_out  = (const float*)d_in[3];
    const float* b_out  = (const float*)d_in[4];
    float* out = (float*)d_out;

    // 1) QKV projection + scatter
    dim3 g1(3*DIM / GBN, MTOK / GBM);
    mma_qkv<<<g1, 256>>>(x, w_qkv, b_qkv);

    // 2) fused attention
    size_t smem = (size_t)4 * 64 * FP * sizeof(uint32_t);  // 73728 B
    cudaFuncSetAttribute(attn_kernel,
                         cudaFuncAttributeMaxDynamicSharedMemorySize, (int)smem);
    dim3 g2(SEQ / QT, NH, BATCH);
    attn_kernel<<<g2, 128, smem>>>();

    // 3) output projection
    dim3 g3(DIM / GBN, MTOK / GBM);
    mma_out<<<g3, 256>>>(w_out, b_out, out);
}

// round 4
// speedup vs baseline: 1.2162x; 1.2162x over previous
#include <cuda_runtime.h>
#include <math.h>
#include <stdint.h>

#define BATCH 4
#define SEQ   2048
#define DIM   1024
#define NH    16
#define HD    64
#define MTOK  (BATCH*SEQ)        // 8192
#define SCALE 0.125f             // 1/sqrt(64)

// Scratch (allocation-free: __device__ globals)
__device__ float g_q[BATCH*NH*SEQ*HD];     // 32 MB
__device__ float g_k[BATCH*NH*SEQ*HD];     // 32 MB
__device__ float g_v[BATCH*NH*SEQ*HD];     // 32 MB
__device__ float g_attn[MTOK*DIM];         // 32 MB

// ---------------------------------------------------------------------------
// tf32 helpers
// ---------------------------------------------------------------------------
__device__ __forceinline__ uint32_t tf32cvt(float x) {
    uint32_t r;
    asm("cvt.rna.tf32.f32 %0, %1;" : "=r"(r) : "f"(x));
    return r;
}

__device__ __forceinline__ void mma_tf32(float c[4],
                                         const uint32_t a[4],
                                         const uint32_t b[2]) {
    asm volatile(
        "mma.sync.aligned.m16n8k8.row.col.f32.tf32.tf32.f32 "
        "{%0,%1,%2,%3},{%4,%5,%6,%7},{%8,%9},{%0,%1,%2,%3};"
        : "+f"(c[0]), "+f"(c[1]), "+f"(c[2]), "+f"(c[3])
        : "r"(a[0]), "r"(a[1]), "r"(a[2]), "r"(a[3]),
          "r"(b[0]), "r"(b[1]));
}

// ---------------------------------------------------------------------------
// tf32 MMA GEMM: block tile 128(M)x256(N), GBK=16, 256 threads = 8 warps
// (2 x 4), warp tile 64x64 = 4x8 m16n8k8 tiles. SMEM pre-converted tf32:
//   A k-major  [16][136]  (136 mod 32 == 8 -> af LDS conflict-free)
//   B row-major[16][264]  (264 mod 32 == 8 -> bf LDS conflict-free)
// Double-buffered (dynamic SMEM, 51200 B).
// ---------------------------------------------------------------------------
#define GBM 128
#define GBN 256
#define GBK 16
#define APG 136
#define BPG 264
#define GSMEM_WORDS (2*GBK*APG + 2*GBK*BPG)

__device__ __forceinline__ void sts_a(uint32_t (*As)[APG], int rA, int cgA,
                                      float4 a0, float4 a1) {
    As[cgA+0][rA] = tf32cvt(a0.x);
    As[cgA+1][rA] = tf32cvt(a0.y);
    As[cgA+2][rA] = tf32cvt(a0.z);
    As[cgA+3][rA] = tf32cvt(a0.w);
    As[cgA+4][rA] = tf32cvt(a1.x);
    As[cgA+5][rA] = tf32cvt(a1.y);
    As[cgA+6][rA] = tf32cvt(a1.z);
    As[cgA+7][rA] = tf32cvt(a1.w);
}

__device__ __forceinline__ void sts_b4(uint32_t (*Bs)[BPG], int rB, int cB,
                                       float4 b) {
    uint4 u;
    u.x = tf32cvt(b.x); u.y = tf32cvt(b.y);
    u.z = tf32cvt(b.z); u.w = tf32cvt(b.w);
    *(uint4*)&Bs[rB][cB] = u;
}

__device__ __forceinline__ void gemm_compute(const uint32_t (*As)[APG],
                                             const uint32_t (*Bs)[BPG],
                                             int wr, int wc, int gid, int q4,
                                             float acc[4][8][4]) {
    #pragma unroll
    for (int ks = 0; ks < 2; ks++) {
        int k = ks*8 + q4;
        uint32_t af[4][4], bf[8][2];
        #pragma unroll
        for (int mt = 0; mt < 4; mt++) {
            int m = wr*64 + mt*16 + gid;
            af[mt][0] = As[k][m];
            af[mt][1] = As[k][m+8];
            af[mt][2] = As[k+4][m];
            af[mt][3] = As[k+4][m+8];
        }
        #pragma unroll
        for (int nt = 0; nt < 8; nt++) {
            int n = wc*64 + nt*8 + gid;
            bf[nt][0] = Bs[k][n];
            bf[nt][1] = Bs[k+4][n];
        }
        #pragma unroll
        for (int mt = 0; mt < 4; mt++)
            #pragma unroll
            for (int nt = 0; nt < 8; nt++)
                mma_tf32(acc[mt][nt], af[mt], bf[nt]);
    }
}

#define GEMM_MAIN(A_, B_, K_, N_)                                              \
    extern __shared__ uint32_t dsm[];                                          \
    uint32_t (*As0)[APG] = (uint32_t (*)[APG])dsm;                             \
    uint32_t (*As1)[APG] = (uint32_t (*)[APG])(dsm + GBK*APG);                 \
    uint32_t (*Bs0)[BPG] = (uint32_t (*)[BPG])(dsm + 2*GBK*APG);               \
    uint32_t (*Bs1)[BPG] = (uint32_t (*)[BPG])(dsm + 2*GBK*APG + GBK*BPG);     \
    int tid  = threadIdx.x;                                                    \
    int lane = tid & 31;                                                       \
    int wid  = tid >> 5;                                                       \
    int wr = wid >> 2, wc = wid & 3, gid = lane >> 2, q4 = lane & 3;           \
    int row0 = blockIdx.y * GBM, col0 = blockIdx.x * GBN;                      \
    int rA = tid >> 1,  cgA = (tid & 1) * 8;                                   \
    int rB = tid >> 4,  cBb = (tid & 15) * 16;                                 \
    float acc[4][8][4];                                                        \
    _Pragma("unroll")                                                          \
    for (int mt = 0; mt < 4; mt++)                                             \
        _Pragma("unroll")                                                      \
        for (int nt = 0; nt < 8; nt++)                                         \
            _Pragma("unroll")                                                  \
            for (int e = 0; e < 4; e++) acc[mt][nt][e] = 0.f;                  \
    const float* aRowPtr = (A_) + (size_t)(row0 + rA) * (K_);                  \
    const float* bRowPtr = (B_) + (size_t)rB * (N_) + col0 + cBb;              \
    float4 a4[2], b4[4];                                                       \
    a4[0] = *(const float4*)&aRowPtr[cgA];                                     \
    a4[1] = *(const float4*)&aRowPtr[cgA + 4];                                 \
    _Pragma("unroll")                                                          \
    for (int j = 0; j < 4; j++) b4[j] = *(const float4*)&bRowPtr[j*4];         \
    sts_a(As0, rA, cgA, a4[0], a4[1]);                                         \
    _Pragma("unroll")                                                          \
    for (int j = 0; j < 4; j++) sts_b4(Bs0, rB, cBb + j*4, b4[j]);             \
    __syncthreads();                                                           \
    int buf = 0;                                                               \
    for (int k0 = GBK; ; k0 += GBK) {                                          \
        bool more = (k0 < (K_));                                               \
        if (more) {                                                            \
            a4[0] = *(const float4*)&aRowPtr[k0 + cgA];                        \
            a4[1] = *(const float4*)&aRowPtr[k0 + cgA + 4];                    \
            _Pragma("unroll")                                                  \
            for (int j = 0; j < 4; j++)                                        \
                b4[j] = *(const float4*)&bRowPtr[(size_t)k0*(N_) + j*4];       \
        }                                                                      \
        gemm_compute(buf ? As1 : As0, buf ? Bs1 : Bs0, wr, wc, gid, q4, acc);  \
        if (!more) break;                                                      \
        if (buf) { sts_a(As0, rA, cgA, a4[0], a4[1]);                          \
                   _Pragma("unroll")                                           \
                   for (int j = 0; j < 4; j++) sts_b4(Bs0, rB, cBb+j*4, b4[j]);\
        } else {   sts_a(As1, rA, cgA, a4[0], a4[1]);                          \
                   _Pragma("unroll")                                           \
                   for (int j = 0; j < 4; j++) sts_b4(Bs1, rB, cBb+j*4, b4[j]);\
        }                                                                      \
        __syncthreads();                                                       \
        buf ^= 1;                                                              \
    }

// QKV projection: C = x @ w_qkv + b_qkv, scattered into g_q/g_k/g_v (B,H,S,Hd)
__global__ void __launch_bounds__(256) mma_qkv(
    const float* __restrict__ A, const float* __restrict__ Bm,
    const float* __restrict__ bias)
{
    GEMM_MAIN(A, Bm, DIM, 3*DIM)

    #pragma unroll
    for (int mt = 0; mt < 4; mt++) {
        #pragma unroll
        for (int nt = 0; nt < 8; nt++) {
            #pragma unroll
            for (int e = 0; e < 4; e++) {
                int row = row0 + wr*64 + mt*16 + gid + (e >> 1) * 8;
                int col = col0 + wc*64 + nt*8 + 2*q4 + (e & 1);
                float v = acc[mt][nt][e] + bias[col];
                int b  = row >> 11;
                int s  = row & 2047;
                int three = col >> 10;
                int rem   = col & 1023;
                int h     = rem >> 6;
                int hd    = rem & 63;
                size_t dst = ((size_t)(b*NH + h)*SEQ + s)*HD + hd;
                if (three == 0)      g_q[dst] = v;
                else if (three == 1) g_k[dst] = v;
                else                 g_v[dst] = v;
            }
        }
    }
}

// Output projection: d_out = g_attn @ w_out + b_out
__global__ void __launch_bounds__(256) mma_out(
    const float* __restrict__ Bm, const float* __restrict__ bias,
    float* __restrict__ C)
{
    const float* A = g_attn;
    GEMM_MAIN(A, Bm, DIM, DIM)

    #pragma unroll
    for (int mt = 0; mt < 4; mt++) {
        #pragma unroll
        for (int nt = 0; nt < 8; nt++) {
            #pragma unroll
            for (int e = 0; e < 4; e++) {
                int row = row0 + wr*64 + mt*16 + gid + (e >> 1) * 8;
                int col = col0 + wc*64 + nt*8 + 2*q4 + (e & 1);
                C[(size_t)row*DIM + col] = acc[mt][nt][e] + bias[col];
            }
        }
    }
}

// ---------------------------------------------------------------------------
// Fused flash attention with tf32 mma. Block = 64 queries of one (b,h),
// 128 threads = 4 warps; warp w owns q-rows [w*16, w*16+16).
// Row-major SMEM staging (vector STS), tf32 pre-converted at store time.
// Pitches: Q/K/P = 68 (bank map 4*gid+q4, conflict-free),
//          V     = 72 (bank map 8*q4+gid, conflict-free).
// Q fragments hoisted out of the key-tile loop.
// ---------------------------------------------------------------------------
#define QT 64
#define KT 64
#define AP 68
#define VP 72
#define ATT_SMEM_WORDS (3*64*AP + 64*VP)

__global__ void __launch_bounds__(128) attn_kernel()
{
    extern __shared__ uint32_t smu[];
    uint32_t (*Qs)[AP] = (uint32_t (*)[AP])smu;               // [q][d]
    uint32_t (*Ks)[AP] = (uint32_t (*)[AP])(smu + 64*AP);     // [key][d]
    uint32_t (*Ps)[AP] = (uint32_t (*)[AP])(smu + 2*64*AP);   // [q][key]
    uint32_t (*Vs)[VP] = (uint32_t (*)[VP])(smu + 3*64*AP);   // [key][d]

    int tid  = threadIdx.x;
    int lane = tid & 31;
    int w    = tid >> 5;     // 0..3
    int gid  = lane >> 2;    // 0..7
    int q4   = lane & 3;     // 0..3
    int m    = w*16 + gid;   // warp-local a-fragment row

    int b  = blockIdx.z;
    int h  = blockIdx.y;
    int q0 = blockIdx.x * QT;

    const float* qptr = g_q + ((size_t)(b*NH + h)*SEQ)*HD;
    const float* kptr = g_k + ((size_t)(b*NH + h)*SEQ)*HD;
    const float* vptr = g_v + ((size_t)(b*NH + h)*SEQ)*HD;

    // load Q tile row-major, scaled + tf32-converted
    #pragma unroll
    for (int it = 0; it < 8; it++) {
        int e  = tid + it*128;
        int r  = e >> 4;
        int c4 = (e & 15) * 4;
        float4 v = *(const float4*)&qptr[(size_t)(q0 + r)*HD + c4];
        uint4 u;
        u.x = tf32cvt(v.x * SCALE); u.y = tf32cvt(v.y * SCALE);
        u.z = tf32cvt(v.z * SCALE); u.w = tf32cvt(v.w * SCALE);
        *(uint4*)&Qs[r][c4] = u;
    }
    __syncthreads();

    // hoist Q fragments (loop-invariant over key tiles)
    uint32_t qf[8][4];
    #pragma unroll
    for (int kk = 0; kk < 8; kk++) {
        int d = kk*8 + q4;
        qf[kk][0] = Qs[m][d];
        qf[kk][1] = Qs[m+8][d];
        qf[kk][2] = Qs[m][d+4];
        qf[kk][3] = Qs[m+8][d+4];
    }

    float m_a = -INFINITY, m_b = -INFINITY;
    float l_a = 0.f, l_b = 0.f;
    float O[8][4];
    #pragma unroll
    for (int dt = 0; dt < 8; dt++)
        #pragma unroll
        for (int e = 0; e < 4; e++) O[dt][e] = 0.f;

    for (int kt = 0; kt < SEQ; kt += KT) {
        // load K/V tiles row-major, tf32-converted
        #pragma unroll
        for (int it = 0; it < 8; it++) {
            int e  = tid + it*128;
            int r  = e >> 4;
            int c4 = (e & 15) * 4;
            float4 kv = *(const float4*)&kptr[(size_t)(kt + r)*HD + c4];
            uint4 u;
            u.x = tf32cvt(kv.x); u.y = tf32cvt(kv.y);
            u.z = tf32cvt(kv.z); u.w = tf32cvt(kv.w);
            *(uint4*)&Ks[r][c4] = u;
            float4 vv = *(const float4*)&vptr[(size_t)(kt + r)*HD + c4];
            u.x = tf32cvt(vv.x); u.y = tf32cvt(vv.y);
            u.z = tf32cvt(vv.z); u.w = tf32cvt(vv.w);
            *(uint4*)&Vs[r][c4] = u;
        }
        __syncthreads();

        // S = Q @ K^T   (warp: 16 rows x 64 keys -> 8 n-tiles)
        float S[8][4];
        #pragma unroll
        for (int nt = 0; nt < 8; nt++)
            #pragma unroll
            for (int e = 0; e < 4; e++) S[nt][e] = 0.f;

        #pragma unroll
        for (int kk = 0; kk < 8; kk++) {
            int d = kk*8 + q4;
            uint32_t bf[8][2];
            #pragma unroll
            for (int nt = 0; nt < 8; nt++) {
                bf[nt][0] = Ks[nt*8 + gid][d];
                bf[nt][1] = Ks[nt*8 + gid][d+4];
            }
            #pragma unroll
            for (int nt = 0; nt < 8; nt++)
                mma_tf32(S[nt], qf[kk], bf[nt]);
        }

        // online softmax (thread owns warp-local rows gid and gid+8)
        {
            float ma = S[0][0], mb = S[0][2];
            #pragma unroll
            for (int nt = 0; nt < 8; nt++) {
                ma = fmaxf(ma, fmaxf(S[nt][0], S[nt][1]));
                mb = fmaxf(mb, fmaxf(S[nt][2], S[nt][3]));
            }
            #pragma unroll
            for (int off = 1; off <= 2; off <<= 1) {
                ma = fmaxf(ma, __shfl_xor_sync(0xffffffffu, ma, off));
                mb = fmaxf(mb, __shfl_xor_sync(0xffffffffu, mb, off));
            }
            float mna = fmaxf(m_a, ma);
            float mnb = fmaxf(m_b, mb);
            float alpha_a = __expf(m_a - mna);
            float alpha_b = __expf(m_b - mnb);
            float sa = 0.f, sb = 0.f;
            #pragma unroll
            for (int nt = 0; nt < 8; nt++) {
                S[nt][0] = __expf(S[nt][0] - mna);
                S[nt][1] = __expf(S[nt][1] - mna);
                S[nt][2] = __expf(S[nt][2] - mnb);
                S[nt][3] = __expf(S[nt][3] - mnb);
                sa += S[nt][0] + S[nt][1];
                sb += S[nt][2] + S[nt][3];
            }
            #pragma unroll
            for (int off = 1; off <= 2; off <<= 1) {
                sa += __shfl_xor_sync(0xffffffffu, sa, off);
                sb += __shfl_xor_sync(0xffffffffu, sb, off);
            }
            l_a = l_a * alpha_a + sa;
            l_b = l_b * alpha_b + sb;
            m_a = mna; m_b = mnb;
            #pragma unroll
            for (int dt = 0; dt < 8; dt++) {
                O[dt][0] *= alpha_a; O[dt][1] *= alpha_a;
                O[dt][2] *= alpha_b; O[dt][3] *= alpha_b;
            }
        }

        // stage P row-major (tf32-converted); warp-private rows
        #pragma unroll
        for (int nt = 0; nt < 8; nt++) {
            int col = nt*8 + 2*q4;
            uint2 ua, ub;
            ua.x = tf32cvt(S[nt][0]); ua.y = tf32cvt(S[nt][1]);
            ub.x = tf32cvt(S[nt][2]); ub.y = tf32cvt(S[nt][3]);
            *(uint2*)&Ps[m][col]   = ua;
            *(uint2*)&Ps[m+8][col] = ub;
        }
        __syncwarp();

        // O += P @ V
        #pragma unroll
        for (int kk = 0; kk < 8; kk++) {
            int kkey = kk*8 + q4;
            uint32_t af[4];
            af[0] = Ps[m][kkey];
            af[1] = Ps[m+8][kkey];
            af[2] = Ps[m][kkey+4];
            af[3] = Ps[m+8][kkey+4];
            uint32_t bf[8][2];
            #pragma unroll
            for (int dt = 0; dt < 8; dt++) {
                bf[dt][0] = Vs[kkey][dt*8 + gid];
                bf[dt][1] = Vs[kkey+4][dt*8 + gid];
            }
            #pragma unroll
            for (int dt = 0; dt < 8; dt++)
                mma_tf32(O[dt], af, bf[dt]);
        }
        __syncthreads();   // before next tile overwrites Ks/Vs
    }

    // write normalized output in (B,S,D) layout for the final GEMM
    float inv_a = 1.f / l_a;
    float inv_b = 1.f / l_b;
    size_t rowbase_a = ((size_t)b*SEQ + q0 + m)*DIM + h*HD;
    size_t rowbase_b = ((size_t)b*SEQ + q0 + m + 8)*DIM + h*HD;
    #pragma unroll
    for (int dt = 0; dt < 8; dt++) {
        int col = dt*8 + 2*q4;
        g_attn[rowbase_a + col]     = O[dt][0] * inv_a;
        g_attn[rowbase_a + col + 1] = O[dt][1] * inv_a;
        g_attn[rowbase_b + col]     = O[dt][2] * inv_b;
        g_attn[rowbase_b + col + 1] = O[dt][3] * inv_b;
    }
}

// ---------------------------------------------------------------------------
extern "C" void kernel_launch(void* const* d_in, const int* in_sizes, int n_in,
                              void* d_out, int out_size)
{
    const float* x      = (const float*)d_in[0];
    const float* w_qkv  = (const float*)d_in[1];
    const float* b_qkv  = (const float*)d_in[2];
    const float* w_out  = (const float*)d_in[3];
    const float* b_out  = (const float*)d_in[4];
    float* out = (float*)d_out;

    size_t gsmem = (size_t)GSMEM_WORDS * sizeof(uint32_t);   // 51200 B
    cudaFuncSetAttribute(mma_qkv,
                         cudaFuncAttributeMaxDynamicSharedMemorySize, (int)gsmem);
    cudaFuncSetAttribute(mma_out,
                         cudaFuncAttributeMaxDynamicSharedMemorySize, (int)gsmem);

    // 1) QKV projection + scatter
    dim3 g1(3*DIM / GBN, MTOK / GBM);
    mma_qkv<<<g1, 256, gsmem>>>(x, w_qkv, b_qkv);

    // 2) fused attention
    size_t asmem = (size_t)ATT_SMEM_WORDS * sizeof(uint32_t);  // 70656 B
    cudaFuncSetAttribute(attn_kernel,
                         cudaFuncAttributeMaxDynamicSharedMemorySize, (int)asmem);
    dim3 g2(SEQ / QT, NH, BATCH);
    attn_kernel<<<g2, 128, asmem>>>();

    // 3) output projection
    dim3 g3(DIM / GBN, MTOK / GBM);
    mma_out<<<g3, 256, gsmem>>>(w_out, b_out, out);
}

// round 6
// speedup vs baseline: 1.3306x; 1.0941x over previous
#include <cuda_runtime.h>
#include <math.h>
#include <stdint.h>

#define BATCH 4
#define SEQ   2048
#define DIM   1024
#define NH    16
#define HD    64
#define MTOK  (BATCH*SEQ)        // 8192
#define SCALE 0.125f             // 1/sqrt(64)

// Scratch (allocation-free: __device__ globals)
__device__ float g_q[BATCH*NH*SEQ*HD];     // 32 MB
__device__ float g_k[BATCH*NH*SEQ*HD];     // 32 MB
__device__ float g_v[BATCH*NH*SEQ*HD];     // 32 MB
__device__ float g_attn[MTOK*DIM];         // 32 MB

// ---------------------------------------------------------------------------
// tf32 helpers
// ---------------------------------------------------------------------------
__device__ __forceinline__ uint32_t tf32cvt(float x) {
    uint32_t r;
    asm("cvt.rna.tf32.f32 %0, %1;" : "=r"(r) : "f"(x));
    return r;
}

__device__ __forceinline__ void mma_tf32(float c[4],
                                         const uint32_t a[4],
                                         const uint32_t b[2]) {
    asm volatile(
        "mma.sync.aligned.m16n8k8.row.col.f32.tf32.tf32.f32 "
        "{%0,%1,%2,%3},{%4,%5,%6,%7},{%8,%9},{%0,%1,%2,%3};"
        : "+f"(c[0]), "+f"(c[1]), "+f"(c[2]), "+f"(c[3])
        : "r"(a[0]), "r"(a[1]), "r"(a[2]), "r"(a[3]),
          "r"(b[0]), "r"(b[1]));
}

// ---------------------------------------------------------------------------
// tf32 MMA GEMM (round-3 measured-best): 128x128 block tile, BK=16,
// 256 threads = 8 warps (2x4), warp tile 64x32. SMEM holds tf32-converted
// operands, k-major, pitch 136 (mod 32 == 8 -> fragment LDS conflict-free).
// Double-buffered.
// ---------------------------------------------------------------------------
#define GBM 128
#define GBN 128
#define GBK 16
#define KP  136

__device__ __forceinline__ void sts_a(uint32_t (*As)[KP], int rA, int cgA,
                                      float4 a0, float4 a1) {
    As[cgA+0][rA] = tf32cvt(a0.x);
    As[cgA+1][rA] = tf32cvt(a0.y);
    As[cgA+2][rA] = tf32cvt(a0.z);
    As[cgA+3][rA] = tf32cvt(a0.w);
    As[cgA+4][rA] = tf32cvt(a1.x);
    As[cgA+5][rA] = tf32cvt(a1.y);
    As[cgA+6][rA] = tf32cvt(a1.z);
    As[cgA+7][rA] = tf32cvt(a1.w);
}

__device__ __forceinline__ void sts_b(uint32_t (*Bs)[KP], int rB, int cB,
                                      float4 b0, float4 b1) {
    uint4 u;
    u.x = tf32cvt(b0.x); u.y = tf32cvt(b0.y);
    u.z = tf32cvt(b0.z); u.w = tf32cvt(b0.w);
    *(uint4*)&Bs[rB][cB] = u;
    u.x = tf32cvt(b1.x); u.y = tf32cvt(b1.y);
    u.z = tf32cvt(b1.z); u.w = tf32cvt(b1.w);
    *(uint4*)&Bs[rB][cB+4] = u;
}

__device__ __forceinline__ void gemm_compute(const uint32_t (*As)[KP],
                                             const uint32_t (*Bs)[KP],
                                             int wr, int wc, int gid, int q4,
                                             float acc[4][4][4]) {
    #pragma unroll
    for (int ks = 0; ks < 2; ks++) {
        int k = ks*8 + q4;
        uint32_t af[4][4], bf[4][2];
        #pragma unroll
        for (int mt = 0; mt < 4; mt++) {
            int m = wr*64 + mt*16 + gid;
            af[mt][0] = As[k][m];
            af[mt][1] = As[k][m+8];
            af[mt][2] = As[k+4][m];
            af[mt][3] = As[k+4][m+8];
        }
        #pragma unroll
        for (int nt = 0; nt < 4; nt++) {
            int n = wc*32 + nt*8 + gid;
            bf[nt][0] = Bs[k][n];
            bf[nt][1] = Bs[k+4][n];
        }
        #pragma unroll
        for (int mt = 0; mt < 4; mt++)
            #pragma unroll
            for (int nt = 0; nt < 4; nt++)
                mma_tf32(acc[mt][nt], af[mt], bf[nt]);
    }
}

#define GEMM_MAIN(A_, B_, K_, N_)                                              \
    __shared__ uint32_t As[2][GBK][KP];                                        \
    __shared__ uint32_t Bs[2][GBK][KP];                                        \
    int tid  = threadIdx.x;                                                    \
    int lane = tid & 31;                                                       \
    int wid  = tid >> 5;                                                       \
    int wr = wid >> 2, wc = wid & 3, gid = lane >> 2, q4 = lane & 3;           \
    int row0 = blockIdx.y * GBM, col0 = blockIdx.x * GBN;                      \
    int rA = tid >> 1,  cgA = (tid & 1) * 8;                                   \
    int rB = tid >> 4,  cB  = (tid & 15) * 8;                                  \
    float acc[4][4][4];                                                        \
    _Pragma("unroll")                                                          \
    for (int mt = 0; mt < 4; mt++)                                             \
        _Pragma("unroll")                                                      \
        for (int nt = 0; nt < 4; nt++)                                         \
            _Pragma("unroll")                                                  \
            for (int e = 0; e < 4; e++) acc[mt][nt][e] = 0.f;                  \
    const float* aRowPtr = (A_) + (size_t)(row0 + rA) * (K_);                  \
    float4 a4[2], b4[2];                                                       \
    a4[0] = *(const float4*)&aRowPtr[cgA];                                     \
    a4[1] = *(const float4*)&aRowPtr[cgA + 4];                                 \
    b4[0] = *(const float4*)&(B_)[(size_t)rB * (N_) + col0 + cB];              \
    b4[1] = *(const float4*)&(B_)[(size_t)rB * (N_) + col0 + cB + 4];          \
    sts_a(As[0], rA, cgA, a4[0], a4[1]);                                       \
    sts_b(Bs[0], rB, cB,  b4[0], b4[1]);                                       \
    __syncthreads();                                                           \
    int buf = 0;                                                               \
    for (int k0 = GBK; ; k0 += GBK) {                                          \
        bool more = (k0 < (K_));                                               \
        if (more) {                                                            \
            a4[0] = *(const float4*)&aRowPtr[k0 + cgA];                        \
            a4[1] = *(const float4*)&aRowPtr[k0 + cgA + 4];                    \
            b4[0] = *(const float4*)&(B_)[(size_t)(k0 + rB)*(N_) + col0 + cB]; \
            b4[1] = *(const float4*)&(B_)[(size_t)(k0 + rB)*(N_) + col0 + cB + 4]; \
        }                                                                      \
        gemm_compute(As[buf], Bs[buf], wr, wc, gid, q4, acc);                  \
        if (!more) break;                                                      \
        sts_a(As[buf^1], rA, cgA, a4[0], a4[1]);                               \
        sts_b(Bs[buf^1], rB, cB,  b4[0], b4[1]);                               \
        __syncthreads();                                                       \
        buf ^= 1;                                                              \
    }

// QKV projection: C = x @ w_qkv + b_qkv, scattered into g_q/g_k/g_v (B,H,S,Hd)
__global__ void __launch_bounds__(256) mma_qkv(
    const float* __restrict__ A, const float* __restrict__ Bm,
    const float* __restrict__ bias)
{
    GEMM_MAIN(A, Bm, DIM, 3*DIM)

    #pragma unroll
    for (int mt = 0; mt < 4; mt++) {
        #pragma unroll
        for (int nt = 0; nt < 4; nt++) {
            #pragma unroll
            for (int e = 0; e < 4; e++) {
                int row = row0 + wr*64 + mt*16 + gid + (e >> 1) * 8;
                int col = col0 + wc*32 + nt*8 + 2*q4 + (e & 1);
                float v = acc[mt][nt][e] + bias[col];
                int b  = row >> 11;
                int s  = row & 2047;
                int three = col >> 10;
                int rem   = col & 1023;
                int h     = rem >> 6;
                int hd    = rem & 63;
                size_t dst = ((size_t)(b*NH + h)*SEQ + s)*HD + hd;
                if (three == 0)      g_q[dst] = v;
                else if (three == 1) g_k[dst] = v;
                else                 g_v[dst] = v;
            }
        }
    }
}

// Output projection: d_out = g_attn @ w_out + b_out
__global__ void __launch_bounds__(256) mma_out(
    const float* __restrict__ Bm, const float* __restrict__ bias,
    float* __restrict__ C)
{
    const float* A = g_attn;
    GEMM_MAIN(A, Bm, DIM, DIM)

    #pragma unroll
    for (int mt = 0; mt < 4; mt++) {
        #pragma unroll
        for (int nt = 0; nt < 4; nt++) {
            #pragma unroll
            for (int e = 0; e < 4; e++) {
                int row = row0 + wr*64 + mt*16 + gid + (e >> 1) * 8;
                int col = col0 + wc*32 + nt*8 + 2*q4 + (e & 1);
                C[(size_t)row*DIM + col] = acc[mt][nt][e] + bias[col];
            }
        }
    }
}

// ---------------------------------------------------------------------------
// Fused flash attention with tf32 mma (round-4 measured-best).
// Block = 64 queries of one (b,h), 128 threads = 4 warps; warp w owns
// q-rows [w*16, w*16+16). Row-major SMEM staging (vector STS), tf32
// pre-converted at store time. Pitches: Q/K/P = 68, V = 72 (conflict-free).
// Q fragments hoisted out of the key-tile loop.
// ---------------------------------------------------------------------------
#define QT 64
#define KT 64
#define AP 68
#define VP 72
#define ATT_SMEM_WORDS (3*64*AP + 64*VP)

__global__ void __launch_bounds__(128) attn_kernel()
{
    extern __shared__ uint32_t smu[];
    uint32_t (*Qs)[AP] = (uint32_t (*)[AP])smu;               // [q][d]
    uint32_t (*Ks)[AP] = (uint32_t (*)[AP])(smu + 64*AP);     // [key][d]
    uint32_t (*Ps)[AP] = (uint32_t (*)[AP])(smu + 2*64*AP);   // [q][key]
    uint32_t (*Vs)[VP] = (uint32_t (*)[VP])(smu + 3*64*AP);   // [key][d]

    int tid  = threadIdx.x;
    int lane = tid & 31;
    int w    = tid >> 5;
    int gid  = lane >> 2;
    int q4   = lane & 3;
    int m    = w*16 + gid;

    int b  = blockIdx.z;
    int h  = blockIdx.y;
    int q0 = blockIdx.x * QT;

    const float* qptr = g_q + ((size_t)(b*NH + h)*SEQ)*HD;
    const float* kptr = g_k + ((size_t)(b*NH + h)*SEQ)*HD;
    const float* vptr = g_v + ((size_t)(b*NH + h)*SEQ)*HD;

    // load Q tile row-major, scaled + tf32-converted
    #pragma unroll
    for (int it = 0; it < 8; it++) {
        int e  = tid + it*128;
        int r  = e >> 4;
        int c4 = (e & 15) * 4;
        float4 v = *(const float4*)&qptr[(size_t)(q0 + r)*HD + c4];
        uint4 u;
        u.x = tf32cvt(v.x * SCALE); u.y = tf32cvt(v.y * SCALE);
        u.z = tf32cvt(v.z * SCALE); u.w = tf32cvt(v.w * SCALE);
        *(uint4*)&Qs[r][c4] = u;
    }
    __syncthreads();

    // hoist Q fragments (loop-invariant over key tiles)
    uint32_t qf[8][4];
    #pragma unroll
    for (int kk = 0; kk < 8; kk++) {
        int d = kk*8 + q4;
        qf[kk][0] = Qs[m][d];
        qf[kk][1] = Qs[m+8][d];
        qf[kk][2] = Qs[m][d+4];
        qf[kk][3] = Qs[m+8][d+4];
    }

    float m_a = -INFINITY, m_b = -INFINITY;
    float l_a = 0.f, l_b = 0.f;
    float O[8][4];
    #pragma unroll
    for (int dt = 0; dt < 8; dt++)
        #pragma unroll
        for (int e = 0; e < 4; e++) O[dt][e] = 0.f;

    for (int kt = 0; kt < SEQ; kt += KT) {
        // load K/V tiles row-major, tf32-converted
        #pragma unroll
        for (int it = 0; it < 8; it++) {
            int e  = tid + it*128;
            int r  = e >> 4;
            int c4 = (e & 15) * 4;
            float4 kv = *(const float4*)&kptr[(size_t)(kt + r)*HD + c4];
            uint4 u;
            u.x = tf32cvt(kv.x); u.y = tf32cvt(kv.y);
            u.z = tf32cvt(kv.z); u.w = tf32cvt(kv.w);
            *(uint4*)&Ks[r][c4] = u;
            float4 vv = *(const float4*)&vptr[(size_t)(kt + r)*HD + c4];
            u.x = tf32cvt(vv.x); u.y = tf32cvt(vv.y);
            u.z = tf32cvt(vv.z); u.w = tf32cvt(vv.w);
            *(uint4*)&Vs[r][c4] = u;
        }
        __syncthreads();

        // S = Q @ K^T   (warp: 16 rows x 64 keys -> 8 n-tiles)
        float S[8][4];
        #pragma unroll
        for (int nt = 0; nt < 8; nt++)
            #pragma unroll
            for (int e = 0; e < 4; e++) S[nt][e] = 0.f;

        #pragma unroll
        for (int kk = 0; kk < 8; kk++) {
            int d = kk*8 + q4;
            uint32_t bf[8][2];
            #pragma unroll
            for (int nt = 0; nt < 8; nt++) {
                bf[nt][0] = Ks[nt*8 + gid][d];
                bf[nt][1] = Ks[nt*8 + gid][d+4];
            }
            #pragma unroll
            for (int nt = 0; nt < 8; nt++)
                mma_tf32(S[nt], qf[kk], bf[nt]);
        }

        // online softmax (thread owns warp-local rows gid and gid+8)
        {
            float ma = S[0][0], mb = S[0][2];
            #pragma unroll
            for (int nt = 0; nt < 8; nt++) {
                ma = fmaxf(ma, fmaxf(S[nt][0], S[nt][1]));
                mb = fmaxf(mb, fmaxf(S[nt][2], S[nt][3]));
            }
            #pragma unroll
            for (int off = 1; off <= 2; off <<= 1) {
                ma = fmaxf(ma, __shfl_xor_sync(0xffffffffu, ma, off));
                mb = fmaxf(mb, __shfl_xor_sync(0xffffffffu, mb, off));
            }
            float mna = fmaxf(m_a, ma);
            float mnb = fmaxf(m_b, mb);
            float alpha_a = __expf(m_a - mna);
            float alpha_b = __expf(m_b - mnb);
            float sa = 0.f, sb = 0.f;
            #pragma unroll
            for (int nt = 0; nt < 8; nt++) {
                S[nt][0] = __expf(S[nt][0] - mna);
                S[nt][1] = __expf(S[nt][1] - mna);
                S[nt][2] = __expf(S[nt][2] - mnb);
                S[nt][3] = __expf(S[nt][3] - mnb);
                sa += S[nt][0] + S[nt][1];
                sb += S[nt][2] + S[nt][3];
            }
            #pragma unroll
            for (int off = 1; off <= 2; off <<= 1) {
                sa += __shfl_xor_sync(0xffffffffu, sa, off);
                sb += __shfl_xor_sync(0xffffffffu, sb, off);
            }
            l_a = l_a * alpha_a + sa;
            l_b = l_b * alpha_b + sb;
            m_a = mna; m_b = mnb;
            #pragma unroll
            for (int dt = 0; dt < 8; dt++) {
                O[dt][0] *= alpha_a; O[dt][1] *= alpha_a;
                O[dt][2] *= alpha_b; O[dt][3] *= alpha_b;
            }
        }

        // stage P row-major (tf32-converted); warp-private rows
        #pragma unroll
        for (int nt = 0; nt < 8; nt++) {
            int col = nt*8 + 2*q4;
            uint2 ua, ub;
            ua.x = tf32cvt(S[nt][0]); ua.y = tf32cvt(S[nt][1]);
            ub.x = tf32cvt(S[nt][2]); ub.y = tf32cvt(S[nt][3]);
            *(uint2*)&Ps[m][col]   = ua;
            *(uint2*)&Ps[m+8][col] = ub;
        }
        __syncwarp();

        // O += P @ V
        #pragma unroll
        for (int kk = 0; kk < 8; kk++) {
            int kkey = kk*8 + q4;
            uint32_t af[4];
            af[0] = Ps[m][kkey];
            af[1] = Ps[m+8][kkey];
            af[2] = Ps[m][kkey+4];
            af[3] = Ps[m+8][kkey+4];
            uint32_t bf[8][2];
            #pragma unroll
            for (int dt = 0; dt < 8; dt++) {
                bf[dt][0] = Vs[kkey][dt*8 + gid];
                bf[dt][1] = Vs[kkey+4][dt*8 + gid];
            }
            #pragma unroll
            for (int dt = 0; dt < 8; dt++)
                mma_tf32(O[dt], af, bf[dt]);
        }
        __syncthreads();
    }

    // write normalized output in (B,S,D) layout for the final GEMM
    float inv_a = 1.f / l_a;
    float inv_b = 1.f / l_b;
    size_t rowbase_a = ((size_t)b*SEQ + q0 + m)*DIM + h*HD;
    size_t rowbase_b = ((size_t)b*SEQ + q0 + m + 8)*DIM + h*HD;
    #pragma unroll
    for (int dt = 0; dt < 8; dt++) {
        int col = dt*8 + 2*q4;
        g_attn[rowbase_a + col]     = O[dt][0] * inv_a;
        g_attn[rowbase_a + col + 1] = O[dt][1] * inv_a;
        g_attn[rowbase_b + col]     = O[dt][2] * inv_b;
        g_attn[rowbase_b + col + 1] = O[dt][3] * inv_b;
    }
}

// ---------------------------------------------------------------------------
extern "C" void kernel_launch(void* const* d_in, const int* in_sizes, int n_in,
                              void* d_out, int out_size)
{
    const float* x      = (const float*)d_in[0];
    const float* w_qkv  = (const float*)d_in[1];
    const float* b_qkv  = (const float*)d_in[2];
    const float* w_out  = (const float*)d_in[3];
    const float* b_out  = (const float*)d_in[4];
    float* out = (float*)d_out;

    // 1) QKV projection + scatter
    dim3 g1(3*DIM / GBN, MTOK / GBM);
    mma_qkv<<<g1, 256>>>(x, w_qkv, b_qkv);

    // 2) fused attention
    size_t asmem = (size_t)ATT_SMEM_WORDS * sizeof(uint32_t);  // 70656 B
    cudaFuncSetAttribute(attn_kernel,
        cudaFuncAttributeMaxDynamicSharedMemorySize, (int)asmem);
    dim3 g2(SEQ / QT, NH, BATCH);
    attn_kernel<<<g2, 128, asmem>>>();

    // 3) output projection
    dim3 g3(DIM / GBN, MTOK / GBM);
    mma_out<<<g3, 256>>>(w_out, b_out, out);
}

// round 7
// speedup vs baseline: 1.4100x; 1.0597x over previous
#include <cuda_runtime.h>
#include <math.h>
#include <stdint.h>

#define BATCH 4
#define SEQ   2048
#define DIM   1024
#define NH    16
#define HD    64
#define MTOK  (BATCH*SEQ)        // 8192
#define SCALE_LOG2E 0.1803368801111204f   // (1/sqrt(64)) * log2(e)

// Scratch (allocation-free: __device__ globals)
__device__ float g_q[BATCH*NH*SEQ*HD];     // 32 MB
__device__ float g_k[BATCH*NH*SEQ*HD];     // 32 MB
__device__ float g_v[BATCH*NH*SEQ*HD];     // 32 MB
__device__ float g_attn[MTOK*DIM];         // 32 MB

// ---------------------------------------------------------------------------
// tf32 helpers
// ---------------------------------------------------------------------------
__device__ __forceinline__ uint32_t tf32cvt(float x) {
    uint32_t r;
    asm("cvt.rna.tf32.f32 %0, %1;" : "=r"(r) : "f"(x));
    return r;
}

__device__ __forceinline__ float ex2f(float x) {
    float r;
    asm("ex2.approx.f32 %0, %1;" : "=f"(r) : "f"(x));
    return r;
}

__device__ __forceinline__ void mma_tf32(float c[4],
                                         const uint32_t a[4],
                                         const uint32_t b[2]) {
    asm volatile(
        "mma.sync.aligned.m16n8k8.row.col.f32.tf32.tf32.f32 "
        "{%0,%1,%2,%3},{%4,%5,%6,%7},{%8,%9},{%0,%1,%2,%3};"
        : "+f"(c[0]), "+f"(c[1]), "+f"(c[2]), "+f"(c[3])
        : "r"(a[0]), "r"(a[1]), "r"(a[2]), "r"(a[3]),
          "r"(b[0]), "r"(b[1]));
}

// ---------------------------------------------------------------------------
// tf32 MMA GEMM (measured-best R3/R6): 128x128 block tile, BK=16,
// 256 threads = 8 warps (2x4), warp tile 64x32. SMEM holds tf32-converted
// operands, k-major, pitch 136. Double-buffered. UNCHANGED from round 6.
// ---------------------------------------------------------------------------
#define GBM 128
#define GBN 128
#define GBK 16
#define KP  136

__device__ __forceinline__ void sts_a(uint32_t (*As)[KP], int rA, int cgA,
                                      float4 a0, float4 a1) {
    As[cgA+0][rA] = tf32cvt(a0.x);
    As[cgA+1][rA] = tf32cvt(a0.y);
    As[cgA+2][rA] = tf32cvt(a0.z);
    As[cgA+3][rA] = tf32cvt(a0.w);
    As[cgA+4][rA] = tf32cvt(a1.x);
    As[cgA+5][rA] = tf32cvt(a1.y);
    As[cgA+6][rA] = tf32cvt(a1.z);
    As[cgA+7][rA] = tf32cvt(a1.w);
}

__device__ __forceinline__ void sts_b(uint32_t (*Bs)[KP], int rB, int cB,
                                      float4 b0, float4 b1) {
    uint4 u;
    u.x = tf32cvt(b0.x); u.y = tf32cvt(b0.y);
    u.z = tf32cvt(b0.z); u.w = tf32cvt(b0.w);
    *(uint4*)&Bs[rB][cB] = u;
    u.x = tf32cvt(b1.x); u.y = tf32cvt(b1.y);
    u.z = tf32cvt(b1.z); u.w = tf32cvt(b1.w);
    *(uint4*)&Bs[rB][cB+4] = u;
}

__device__ __forceinline__ void gemm_compute(const uint32_t (*As)[KP],
                                             const uint32_t (*Bs)[KP],
                                             int wr, int wc, int gid, int q4,
                                             float acc[4][4][4]) {
    #pragma unroll
    for (int ks = 0; ks < 2; ks++) {
        int k = ks*8 + q4;
        uint32_t af[4][4], bf[4][2];
        #pragma unroll
        for (int mt = 0; mt < 4; mt++) {
            int m = wr*64 + mt*16 + gid;
            af[mt][0] = As[k][m];
            af[mt][1] = As[k][m+8];
            af[mt][2] = As[k+4][m];
            af[mt][3] = As[k+4][m+8];
        }
        #pragma unroll
        for (int nt = 0; nt < 4; nt++) {
            int n = wc*32 + nt*8 + gid;
            bf[nt][0] = Bs[k][n];
            bf[nt][1] = Bs[k+4][n];
        }
        #pragma unroll
        for (int mt = 0; mt < 4; mt++)
            #pragma unroll
            for (int nt = 0; nt < 4; nt++)
                mma_tf32(acc[mt][nt], af[mt], bf[nt]);
    }
}

#define GEMM_MAIN(A_, B_, K_, N_)                                              \
    __shared__ uint32_t As[2][GBK][KP];                                        \
    __shared__ uint32_t Bs[2][GBK][KP];                                        \
    int tid  = threadIdx.x;                                                    \
    int lane = tid & 31;                                                       \
    int wid  = tid >> 5;                                                       \
    int wr = wid >> 2, wc = wid & 3, gid = lane >> 2, q4 = lane & 3;           \
    int row0 = blockIdx.y * GBM, col0 = blockIdx.x * GBN;                      \
    int rA = tid >> 1,  cgA = (tid & 1) * 8;                                   \
    int rB = tid >> 4,  cB  = (tid & 15) * 8;                                  \
    float acc[4][4][4];                                                        \
    _Pragma("unroll")                                                          \
    for (int mt = 0; mt < 4; mt++)                                             \
        _Pragma("unroll")                                                      \
        for (int nt = 0; nt < 4; nt++)                                         \
            _Pragma("unroll")                                                  \
            for (int e = 0; e < 4; e++) acc[mt][nt][e] = 0.f;                  \
    const float* aRowPtr = (A_) + (size_t)(row0 + rA) * (K_);                  \
    float4 a4[2], b4[2];                                                       \
    a4[0] = *(const float4*)&aRowPtr[cgA];                                     \
    a4[1] = *(const float4*)&aRowPtr[cgA + 4];                                 \
    b4[0] = *(const float4*)&(B_)[(size_t)rB * (N_) + col0 + cB];              \
    b4[1] = *(const float4*)&(B_)[(size_t)rB * (N_) + col0 + cB + 4];          \
    sts_a(As[0], rA, cgA, a4[0], a4[1]);                                       \
    sts_b(Bs[0], rB, cB,  b4[0], b4[1]);                                       \
    __syncthreads();                                                           \
    int buf = 0;                                                               \
    for (int k0 = GBK; ; k0 += GBK) {                                          \
        bool more = (k0 < (K_));                                               \
        if (more) {                                                            \
            a4[0] = *(const float4*)&aRowPtr[k0 + cgA];                        \
            a4[1] = *(const float4*)&aRowPtr[k0 + cgA + 4];                    \
            b4[0] = *(const float4*)&(B_)[(size_t)(k0 + rB)*(N_) + col0 + cB]; \
            b4[1] = *(const float4*)&(B_)[(size_t)(k0 + rB)*(N_) + col0 + cB + 4]; \
        }                                                                      \
        gemm_compute(As[buf], Bs[buf], wr, wc, gid, q4, acc);                  \
        if (!more) break;                                                      \
        sts_a(As[buf^1], rA, cgA, a4[0], a4[1]);                               \
        sts_b(Bs[buf^1], rB, cB,  b4[0], b4[1]);                               \
        __syncthreads();                                                       \
        buf ^= 1;                                                              \
    }

// QKV projection: C = x @ w_qkv + b_qkv, scattered into g_q/g_k/g_v (B,H,S,Hd)
__global__ void __launch_bounds__(256) mma_qkv(
    const float* __restrict__ A, const float* __restrict__ Bm,
    const float* __restrict__ bias)
{
    GEMM_MAIN(A, Bm, DIM, 3*DIM)

    #pragma unroll
    for (int mt = 0; mt < 4; mt++) {
        #pragma unroll
        for (int nt = 0; nt < 4; nt++) {
            #pragma unroll
            for (int e = 0; e < 4; e++) {
                int row = row0 + wr*64 + mt*16 + gid + (e >> 1) * 8;
                int col = col0 + wc*32 + nt*8 + 2*q4 + (e & 1);
                float v = acc[mt][nt][e] + bias[col];
                int b  = row >> 11;
                int s  = row & 2047;
                int three = col >> 10;
                int rem   = col & 1023;
                int h     = rem >> 6;
                int hd    = rem & 63;
                size_t dst = ((size_t)(b*NH + h)*SEQ + s)*HD + hd;
                if (three == 0)      g_q[dst] = v;
                else if (three == 1) g_k[dst] = v;
                else                 g_v[dst] = v;
            }
        }
    }
}

// Output projection: d_out = g_attn @ w_out + b_out
__global__ void __launch_bounds__(256) mma_out(
    const float* __restrict__ Bm, const float* __restrict__ bias,
    float* __restrict__ C)
{
    const float* A = g_attn;
    GEMM_MAIN(A, Bm, DIM, DIM)

    #pragma unroll
    for (int mt = 0; mt < 4; mt++) {
        #pragma unroll
        for (int nt = 0; nt < 4; nt++) {
            #pragma unroll
            for (int e = 0; e < 4; e++) {
                int row = row0 + wr*64 + mt*16 + gid + (e >> 1) * 8;
                int col = col0 + wc*32 + nt*8 + 2*q4 + (e & 1);
                C[(size_t)row*DIM + col] = acc[mt][nt][e] + bias[col];
            }
        }
    }
}

// ---------------------------------------------------------------------------
// Fused flash attention v2: QT=128 queries per CTA, 128 threads = 4 warps,
// warp w owns 32 q-rows [w*32, w*32+32) as 2 m16 tiles (mt=0,1).
// bf K/V fragments amortized over 2 mt tiles -> 1.8x less fragment LDS/query.
// Row-major SMEM staging, tf32 pre-converted. Pitches: Q/K/P=68, V=72.
// Q fragments hoisted; softmax in exp2 domain (Q pre-scaled by log2e/8).
// ---------------------------------------------------------------------------
#define QT 128
#define KT 64
#define AP 68
#define VP 72
#define ATT_SMEM_WORDS (QT*AP + KT*AP + QT*AP + KT*VP)  // Q,K,P,V = 26368

__global__ void __launch_bounds__(128, 2) attn_kernel()
{
    extern __shared__ uint32_t smu[];
    uint32_t (*Qs)[AP] = (uint32_t (*)[AP])smu;                       // [128 q][d]
    uint32_t (*Ks)[AP] = (uint32_t (*)[AP])(smu + QT*AP);             // [64 key][d]
    uint32_t (*Ps)[AP] = (uint32_t (*)[AP])(smu + QT*AP + KT*AP);     // [128 q][key]
    uint32_t (*Vs)[VP] = (uint32_t (*)[VP])(smu + 2*QT*AP + KT*AP);   // [64 key][d]

    int tid  = threadIdx.x;
    int lane = tid & 31;
    int w    = tid >> 5;
    int gid  = lane >> 2;
    int q4   = lane & 3;

    int b  = blockIdx.z;
    int h  = blockIdx.y;
    int q0 = blockIdx.x * QT;

    const float* qptr = g_q + ((size_t)(b*NH + h)*SEQ)*HD;
    const float* kptr = g_k + ((size_t)(b*NH + h)*SEQ)*HD;
    const float* vptr = g_v + ((size_t)(b*NH + h)*SEQ)*HD;

    // load Q tile (128x64) row-major, scaled by log2e/8, tf32-converted
    #pragma unroll
    for (int it = 0; it < 16; it++) {
        int e  = tid + it*128;
        int r  = e >> 4;
        int c4 = (e & 15) * 4;
        float4 v = *(const float4*)&qptr[(size_t)(q0 + r)*HD + c4];
        uint4 u;
        u.x = tf32cvt(v.x * SCALE_LOG2E); u.y = tf32cvt(v.y * SCALE_LOG2E);
        u.z = tf32cvt(v.z * SCALE_LOG2E); u.w = tf32cvt(v.w * SCALE_LOG2E);
        *(uint4*)&Qs[r][c4] = u;
    }
    __syncthreads();

    // hoist Q fragments (loop-invariant): qf[kk][mt][4]
    uint32_t qf[8][2][4];
    #pragma unroll
    for (int kk = 0; kk < 8; kk++) {
        int d = kk*8 + q4;
        #pragma unroll
        for (int mt = 0; mt < 2; mt++) {
            int r = w*32 + mt*16 + gid;
            qf[kk][mt][0] = Qs[r][d];
            qf[kk][mt][1] = Qs[r+8][d];
            qf[kk][mt][2] = Qs[r][d+4];
            qf[kk][mt][3] = Qs[r+8][d+4];
        }
    }

    float m_a[2], m_b[2], l_a[2], l_b[2];
    float O[2][8][4];
    #pragma unroll
    for (int mt = 0; mt < 2; mt++) {
        m_a[mt] = -INFINITY; m_b[mt] = -INFINITY;
        l_a[mt] = 0.f; l_b[mt] = 0.f;
        #pragma unroll
        for (int dt = 0; dt < 8; dt++)
            #pragma unroll
            for (int e = 0; e < 4; e++) O[mt][dt][e] = 0.f;
    }

    for (int kt = 0; kt < SEQ; kt += KT) {
        // load K/V tiles (64x64 each) row-major, tf32-converted
        #pragma unroll
        for (int it = 0; it < 8; it++) {
            int e  = tid + it*128;
            int r  = e >> 4;
            int c4 = (e & 15) * 4;
            float4 kv = *(const float4*)&kptr[(size_t)(kt + r)*HD + c4];
            uint4 u;
            u.x = tf32cvt(kv.x); u.y = tf32cvt(kv.y);
            u.z = tf32cvt(kv.z); u.w = tf32cvt(kv.w);
            *(uint4*)&Ks[r][c4] = u;
            float4 vv = *(const float4*)&vptr[(size_t)(kt + r)*HD + c4];
            u.x = tf32cvt(vv.x); u.y = tf32cvt(vv.y);
            u.z = tf32cvt(vv.z); u.w = tf32cvt(vv.w);
            *(uint4*)&Vs[r][c4] = u;
        }
        __syncthreads();

        // S = Q @ K^T  (warp: 32 rows x 64 keys; bf shared across mt)
        float S[2][8][4];
        #pragma unroll
        for (int mt = 0; mt < 2; mt++)
            #pragma unroll
            for (int nt = 0; nt < 8; nt++)
                #pragma unroll
                for (int e = 0; e < 4; e++) S[mt][nt][e] = 0.f;

        #pragma unroll
        for (int kk = 0; kk < 8; kk++) {
            int d = kk*8 + q4;
            uint32_t bf[8][2];
            #pragma unroll
            for (int nt = 0; nt < 8; nt++) {
                bf[nt][0] = Ks[nt*8 + gid][d];
                bf[nt][1] = Ks[nt*8 + gid][d+4];
            }
            #pragma unroll
            for (int mt = 0; mt < 2; mt++)
                #pragma unroll
                for (int nt = 0; nt < 8; nt++)
                    mma_tf32(S[mt][nt], qf[kk][mt], bf[nt]);
        }

        // online softmax in exp2 domain (per mt; rows gid / gid+8 of tile)
        #pragma unroll
        for (int mt = 0; mt < 2; mt++) {
            float ma = S[mt][0][0], mb = S[mt][0][2];
            #pragma unroll
            for (int nt = 0; nt < 8; nt++) {
                ma = fmaxf(ma, fmaxf(S[mt][nt][0], S[mt][nt][1]));
                mb = fmaxf(mb, fmaxf(S[mt][nt][2], S[mt][nt][3]));
            }
            #pragma unroll
            for (int off = 1; off <= 2; off <<= 1) {
                ma = fmaxf(ma, __shfl_xor_sync(0xffffffffu, ma, off));
                mb = fmaxf(mb, __shfl_xor_sync(0xffffffffu, mb, off));
            }
            float mna = fmaxf(m_a[mt], ma);
            float mnb = fmaxf(m_b[mt], mb);
            float alpha_a = ex2f(m_a[mt] - mna);
            float alpha_b = ex2f(m_b[mt] - mnb);
            float sa = 0.f, sb = 0.f;
            #pragma unroll
            for (int nt = 0; nt < 8; nt++) {
                S[mt][nt][0] = ex2f(S[mt][nt][0] - mna);
                S[mt][nt][1] = ex2f(S[mt][nt][1] - mna);
                S[mt][nt][2] = ex2f(S[mt][nt][2] - mnb);
                S[mt][nt][3] = ex2f(S[mt][nt][3] - mnb);
                sa += S[mt][nt][0] + S[mt][nt][1];
                sb += S[mt][nt][2] + S[mt][nt][3];
            }
            #pragma unroll
            for (int off = 1; off <= 2; off <<= 1) {
                sa += __shfl_xor_sync(0xffffffffu, sa, off);
                sb += __shfl_xor_sync(0xffffffffu, sb, off);
            }
            l_a[mt] = l_a[mt] * alpha_a + sa;
            l_b[mt] = l_b[mt] * alpha_b + sb;
            m_a[mt] = mna; m_b[mt] = mnb;
            #pragma unroll
            for (int dt = 0; dt < 8; dt++) {
                O[mt][dt][0] *= alpha_a; O[mt][dt][1] *= alpha_a;
                O[mt][dt][2] *= alpha_b; O[mt][dt][3] *= alpha_b;
            }
        }

        // stage P row-major (tf32); warp-private rows [w*32, w*32+32)
        #pragma unroll
        for (int mt = 0; mt < 2; mt++) {
            int r = w*32 + mt*16 + gid;
            #pragma unroll
            for (int nt = 0; nt < 8; nt++) {
                int col = nt*8 + 2*q4;
                uint2 ua, ub;
                ua.x = tf32cvt(S[mt][nt][0]); ua.y = tf32cvt(S[mt][nt][1]);
                ub.x = tf32cvt(S[mt][nt][2]); ub.y = tf32cvt(S[mt][nt][3]);
                *(uint2*)&Ps[r][col]   = ua;
                *(uint2*)&Ps[r+8][col] = ub;
            }
        }
        __syncwarp();

        // O += P @ V  (bf shared across mt)
        #pragma unroll
        for (int kk = 0; kk < 8; kk++) {
            int kkey = kk*8 + q4;
            uint32_t af[2][4];
            #pragma unroll
            for (int mt = 0; mt < 2; mt++) {
                int r = w*32 + mt*16 + gid;
                af[mt][0] = Ps[r][kkey];
                af[mt][1] = Ps[r+8][kkey];
                af[mt][2] = Ps[r][kkey+4];
                af[mt][3] = Ps[r+8][kkey+4];
            }
            uint32_t bf[8][2];
            #pragma unroll
            for (int dt = 0; dt < 8; dt++) {
                bf[dt][0] = Vs[kkey][dt*8 + gid];
                bf[dt][1] = Vs[kkey+4][dt*8 + gid];
            }
            #pragma unroll
            for (int mt = 0; mt < 2; mt++)
                #pragma unroll
                for (int dt = 0; dt < 8; dt++)
                    mma_tf32(O[mt][dt], af[mt], bf[dt]);
        }
        __syncthreads();
    }

    // write normalized output in (B,S,D) layout for the final GEMM
    #pragma unroll
    for (int mt = 0; mt < 2; mt++) {
        float inv_a = 1.f / l_a[mt];
        float inv_b = 1.f / l_b[mt];
        int r = w*32 + mt*16 + gid;
        size_t rowbase_a = ((size_t)b*SEQ + q0 + r)*DIM + h*HD;
        size_t rowbase_b = ((size_t)b*SEQ + q0 + r + 8)*DIM + h*HD;
        #pragma unroll
        for (int dt = 0; dt < 8; dt++) {
            int col = dt*8 + 2*q4;
            g_attn[rowbase_a + col]     = O[mt][dt][0] * inv_a;
            g_attn[rowbase_a + col + 1] = O[mt][dt][1] * inv_a;
            g_attn[rowbase_b + col]     = O[mt][dt][2] * inv_b;
            g_attn[rowbase_b + col + 1] = O[mt][dt][3] * inv_b;
        }
    }
}

// ---------------------------------------------------------------------------
extern "C" void kernel_launch(void* const* d_in, const int* in_sizes, int n_in,
                              void* d_out, int out_size)
{
    const float* x      = (const float*)d_in[0];
    const float* w_qkv  = (const float*)d_in[1];
    const float* b_qkv  = (const float*)d_in[2];
    const float* w_out  = (const float*)d_in[3];
    const float* b_out  = (const float*)d_in[4];
    float* out = (float*)d_out;

    // 1) QKV projection + scatter
    dim3 g1(3*DIM / GBN, MTOK / GBM);
    mma_qkv<<<g1, 256>>>(x, w_qkv, b_qkv);

    // 2) fused attention
    size_t asmem = (size_t)ATT_SMEM_WORDS * sizeof(uint32_t);  // 105472 B
    cudaFuncSetAttribute(attn_kernel,
        cudaFuncAttributeMaxDynamicSharedMemorySize, (int)asmem);
    dim3 g2(SEQ / QT, NH, BATCH);
    attn_kernel<<<g2, 128, asmem>>>();

    // 3) output projection
    dim3 g3(DIM / GBN, MTOK / GBM);
    mma_out<<<g3, 256>>>(w_out, b_out, out);
}

// round 8
// speedup vs baseline: 2.1744x; 1.5421x over previous
#include <cuda_runtime.h>
#include <cuda_fp16.h>
#include <math.h>
#include <stdint.h>

#define BATCH 4
#define SEQ   2048
#define DIM   1024
#define NH    16
#define HD    64
#define MTOK  (BATCH*SEQ)        // 8192
#define SCALE_LOG2E 0.1803368801111204f   // (1/sqrt(64)) * log2(e)

// Scratch (allocation-free: __device__ globals), all fp16
__device__ __half g_wqkvT[3*DIM*DIM];      // [3072][1024] = w_qkv^T
__device__ __half g_woutT[DIM*DIM];        // [1024][1024] = w_out^T
__device__ __half g_q[BATCH*NH*SEQ*HD];    // (B,H,S,Hd), pre-scaled by log2e/8
__device__ __half g_k[BATCH*NH*SEQ*HD];
__device__ __half g_v[BATCH*NH*SEQ*HD];
__device__ __half g_attn[MTOK*DIM];        // (B*S, D)

// ---------------------------------------------------------------------------
// helpers
// ---------------------------------------------------------------------------
__device__ __forceinline__ uint32_t f2h2(float lo, float hi) {
    __half2 h = __floats2half2_rn(lo, hi);   // lo -> low 16 bits
    return *reinterpret_cast<uint32_t*>(&h);
}

__device__ __forceinline__ float ex2f(float x) {
    float r;
    asm("ex2.approx.f32 %0, %1;" : "=f"(r) : "f"(x));
    return r;
}

__device__ __forceinline__ void mma_f16(float c[4],
                                        const uint32_t a[4],
                                        const uint32_t b[2]) {
    asm volatile(
        "mma.sync.aligned.m16n8k16.row.col.f32.f16.f16.f32 "
        "{%0,%1,%2,%3},{%4,%5,%6,%7},{%8,%9},{%0,%1,%2,%3};"
        : "+f"(c[0]), "+f"(c[1]), "+f"(c[2]), "+f"(c[3])
        : "r"(a[0]), "r"(a[1]), "r"(a[2]), "r"(a[3]),
          "r"(b[0]), "r"(b[1]));
}

// ---------------------------------------------------------------------------
// prep: transpose fp32 weight [K][N] -> fp16 [N][K]
// ---------------------------------------------------------------------------
__global__ void wtrans(const float* __restrict__ src, __half* __restrict__ dst,
                       int K, int N)
{
    __shared__ float sm[32][33];
    int tx = threadIdx.x, ty = threadIdx.y;
    int n0 = blockIdx.x * 32, k0 = blockIdx.y * 32;
    #pragma unroll
    for (int j = 0; j < 32; j += 8)
        sm[ty + j][tx] = src[(size_t)(k0 + ty + j)*N + n0 + tx];
    __syncthreads();
    #pragma unroll
    for (int j = 0; j < 32; j += 8)
        dst[(size_t)(n0 + ty + j)*K + k0 + tx] = __float2half(sm[tx][ty + j]);
}

// ---------------------------------------------------------------------------
// fp16 MMA GEMM: 128x128 block, BK=32 halves, 256 threads = 8 warps (2x4),
// warp tile 64x32 = 4x4 m16n8k16. SMEM word layout [row][k-word], pitch 20
// (bank map 4*gid+q4 -> conflict-free fragment LDS). Double-buffered.
// A from fp32 GMEM (cvt at STS) or fp16 GMEM; B from pre-transposed fp16.
// ---------------------------------------------------------------------------
#define KPW 20
#define NKB (DIM/32)   // 32

__device__ __forceinline__ void comp16(const uint32_t (*As)[KPW],
                                       const uint32_t (*Bs)[KPW],
                                       int wr, int wc, int gid, int q4,
                                       float acc[4][4][4]) {
    #pragma unroll
    for (int st = 0; st < 2; st++) {
        int kb = st*8 + q4;
        uint32_t af[4][4], bf[4][2];
        #pragma unroll
        for (int mt = 0; mt < 4; mt++) {
            int m = wr*64 + mt*16 + gid;
            af[mt][0] = As[m][kb];
            af[mt][1] = As[m+8][kb];
            af[mt][2] = As[m][kb+4];
            af[mt][3] = As[m+8][kb+4];
        }
        #pragma unroll
        for (int nt = 0; nt < 4; nt++) {
            int n = wc*32 + nt*8 + gid;
            bf[nt][0] = Bs[n][kb];
            bf[nt][1] = Bs[n][kb+4];
        }
        #pragma unroll
        for (int mt = 0; mt < 4; mt++)
            #pragma unroll
            for (int nt = 0; nt < 4; nt++)
                mma_f16(acc[mt][nt], af[mt], bf[nt]);
    }
}

__device__ __forceinline__ void sts_a32(uint32_t (*As)[KPW], int r, int h,
                                        const float4* q) {
    uint4 u;
    u.x = f2h2(q[0].x, q[0].y); u.y = f2h2(q[0].z, q[0].w);
    u.z = f2h2(q[1].x, q[1].y); u.w = f2h2(q[1].z, q[1].w);
    *(uint4*)&As[r][8*h] = u;
    u.x = f2h2(q[2].x, q[2].y); u.y = f2h2(q[2].z, q[2].w);
    u.z = f2h2(q[3].x, q[3].y); u.w = f2h2(q[3].z, q[3].w);
    *(uint4*)&As[r][8*h + 4] = u;
}

__device__ __forceinline__ void sts_h16(uint32_t (*S)[KPW], int r, int h,
                                        uint4 u0, uint4 u1) {
    *(uint4*)&S[r][8*h]     = u0;
    *(uint4*)&S[r][8*h + 4] = u1;
}

// ---- qkv GEMM: x(fp32) @ wqkvT(fp16) + bias -> scatter g_q/g_k/g_v (fp16)
__global__ void __launch_bounds__(256) gemm_qkv(
    const float* __restrict__ A, const float* __restrict__ bias)
{
    __shared__ uint32_t As[2][128][KPW];
    __shared__ uint32_t Bs[2][128][KPW];
    int tid = threadIdx.x, lane = tid & 31, wid = tid >> 5;
    int wr = wid >> 2, wc = wid & 3, gid = lane >> 2, q4 = lane & 3;
    int row0 = blockIdx.y * 128, col0 = blockIdx.x * 128;
    int r = tid >> 1, h = tid & 1;

    float acc[4][4][4];
    #pragma unroll
    for (int mt = 0; mt < 4; mt++)
        #pragma unroll
        for (int nt = 0; nt < 4; nt++)
            #pragma unroll
            for (int e = 0; e < 4; e++) acc[mt][nt][e] = 0.f;

    const float* aRow = A + (size_t)(row0 + r)*DIM + 16*h;
    const __half* bRow = g_wqkvT + (size_t)(col0 + r)*DIM + 16*h;

    float4 aq[4]; uint4 b0, b1;
    #pragma unroll
    for (int j = 0; j < 4; j++) aq[j] = *(const float4*)&aRow[4*j];
    b0 = *(const uint4*)&bRow[0];
    b1 = *(const uint4*)&bRow[8];
    sts_a32(As[0], r, h, aq);
    sts_h16(Bs[0], r, h, b0, b1);
    __syncthreads();

    int buf = 0;
    for (int kb = 1; ; kb++) {
        bool more = (kb < NKB);
        if (more) {
            #pragma unroll
            for (int j = 0; j < 4; j++) aq[j] = *(const float4*)&aRow[kb*32 + 4*j];
            b0 = *(const uint4*)&bRow[kb*32];
            b1 = *(const uint4*)&bRow[kb*32 + 8];
        }
        comp16(As[buf], Bs[buf], wr, wc, gid, q4, acc);
        if (!more) break;
        sts_a32(As[buf^1], r, h, aq);
        sts_h16(Bs[buf^1], r, h, b0, b1);
        __syncthreads();
        buf ^= 1;
    }

    // epilogue: +bias, scatter as half2 (cols 2q4,2q4+1 adjacent, even)
    #pragma unroll
    for (int mt = 0; mt < 4; mt++) {
        #pragma unroll
        for (int nt = 0; nt < 4; nt++) {
            int col = col0 + wc*32 + nt*8 + 2*q4;
            float2 bs = *(const float2*)&bias[col];
            int three = col >> 10;
            int rem   = col & 1023;
            int hh    = rem >> 6;
            int hd    = rem & 63;
            float sc = (three == 0) ? SCALE_LOG2E : 1.f;
            __half* dstb = (three == 0) ? g_q : (three == 1) ? g_k : g_v;
            #pragma unroll
            for (int half_i = 0; half_i < 2; half_i++) {
                int row = row0 + wr*64 + mt*16 + gid + half_i*8;
                int b  = row >> 11;
                int s  = row & 2047;
                float v0 = (acc[mt][nt][2*half_i]   + bs.x) * sc;
                float v1 = (acc[mt][nt][2*half_i+1] + bs.y) * sc;
                size_t dst = ((size_t)(b*NH + hh)*SEQ + s)*HD + hd;
                *(uint32_t*)&dstb[dst] = f2h2(v0, v1);
            }
        }
    }
}

// ---- out GEMM: g_attn(fp16) @ woutT(fp16) + bias -> d_out (fp32)
__global__ void __launch_bounds__(256) gemm_out(
    const float* __restrict__ bias, float* __restrict__ C)
{
    __shared__ uint32_t As[2][128][KPW];
    __shared__ uint32_t Bs[2][128][KPW];
    int tid = threadIdx.x, lane = tid & 31, wid = tid >> 5;
    int wr = wid >> 2, wc = wid & 3, gid = lane >> 2, q4 = lane & 3;
    int row0 = blockIdx.y * 128, col0 = blockIdx.x * 128;
    int r = tid >> 1, h = tid & 1;

    float acc[4][4][4];
    #pragma unroll
    for (int mt = 0; mt < 4; mt++)
        #pragma unroll
        for (int nt = 0; nt < 4; nt++)
            #pragma unroll
            for (int e = 0; e < 4; e++) acc[mt][nt][e] = 0.f;

    const __half* aRow = g_attn  + (size_t)(row0 + r)*DIM + 16*h;
    const __half* bRow = g_woutT + (size_t)(col0 + r)*DIM + 16*h;

    uint4 a0, a1, b0, b1;
    a0 = *(const uint4*)&aRow[0]; a1 = *(const uint4*)&aRow[8];
    b0 = *(const uint4*)&bRow[0]; b1 = *(const uint4*)&bRow[8];
    sts_h16(As[0], r, h, a0, a1);
    sts_h16(Bs[0], r, h, b0, b1);
    __syncthreads();

    int buf = 0;
    for (int kb = 1; ; kb++) {
        bool more = (kb < NKB);
        if (more) {
            a0 = *(const uint4*)&aRow[kb*32]; a1 = *(const uint4*)&aRow[kb*32 + 8];
            b0 = *(const uint4*)&bRow[kb*32]; b1 = *(const uint4*)&bRow[kb*32 + 8];
        }
        comp16(As[buf], Bs[buf], wr, wc, gid, q4, acc);
        if (!more) break;
        sts_h16(As[buf^1], r, h, a0, a1);
        sts_h16(Bs[buf^1], r, h, b0, b1);
        __syncthreads();
        buf ^= 1;
    }

    #pragma unroll
    for (int mt = 0; mt < 4; mt++) {
        #pragma unroll
        for (int nt = 0; nt < 4; nt++) {
            int col = col0 + wc*32 + nt*8 + 2*q4;
            float2 bs = *(const float2*)&bias[col];
            #pragma unroll
            for (int half_i = 0; half_i < 2; half_i++) {
                int row = row0 + wr*64 + mt*16 + gid + half_i*8;
                float2 v;
                v.x = acc[mt][nt][2*half_i]   + bs.x;
                v.y = acc[mt][nt][2*half_i+1] + bs.y;
                *(float2*)&C[(size_t)row*DIM + col] = v;
            }
        }
    }
}

// ---------------------------------------------------------------------------
// Fused flash attention, fp16 m16n8k16. QT=128, 128 threads = 4 warps,
// warp owns 32 q-rows (2 m16 tiles). All SMEM tiles are half2-word arrays,
// pitch 36 (bank map 4*gid+q4 conflict-free). V stored transposed [d][key]
// with word-XOR swizzle (kw ^ ((row>>3)<<2)) -> conflict-free STS and LDS.
// Q pre-scaled (in qkv epilogue); softmax in exp2 domain.
// ---------------------------------------------------------------------------
#define QT 128
#define KT 64
#define PW 36
#define ATT_SMEM_WORDS ((QT + KT + QT + KT) * PW)   // 13824 words = 55296 B

__global__ void __launch_bounds__(128, 2) attn_kernel()
{
    extern __shared__ uint32_t smu[];
    uint32_t (*Qs)[PW] = (uint32_t (*)[PW])smu;                    // [128 q][32 dw]
    uint32_t (*Ks)[PW] = (uint32_t (*)[PW])(smu + QT*PW);          // [64 key][32 dw]
    uint32_t (*Ps)[PW] = (uint32_t (*)[PW])(smu + (QT+KT)*PW);     // [128 q][32 kw]
    uint32_t* Vf       = smu + (2*QT+KT)*PW;                       // [64 d][32 kw] swizzled

    int tid  = threadIdx.x;
    int lane = tid & 31;
    int w    = tid >> 5;
    int gid  = lane >> 2;
    int q4   = lane & 3;

    int b  = blockIdx.z;
    int h  = blockIdx.y;
    int q0 = blockIdx.x * QT;

    const __half* qptr = g_q + ((size_t)(b*NH + h)*SEQ)*HD;
    const __half* kptr = g_k + ((size_t)(b*NH + h)*SEQ)*HD;
    const __half* vptr = g_v + ((size_t)(b*NH + h)*SEQ)*HD;

    // load Q tile (128x64 halves) via uint4 copies
    #pragma unroll
    for (int it = 0; it < 8; it++) {
        int u  = tid + it*128;
        int r  = u >> 3;
        int cu = u & 7;
        uint4 v = *(const uint4*)&qptr[(size_t)(q0 + r)*HD + cu*8];
        *(uint4*)&Qs[r][cu*4] = v;
    }
    __syncthreads();

    // hoist Q fragments: 4 k16 steps over d=64
    uint32_t qf[4][2][4];
    #pragma unroll
    for (int kk = 0; kk < 4; kk++) {
        int kb = kk*8 + q4;
        #pragma unroll
        for (int mt = 0; mt < 2; mt++) {
            int rr = w*32 + mt*16 + gid;
            qf[kk][mt][0] = Qs[rr][kb];
            qf[kk][mt][1] = Qs[rr+8][kb];
            qf[kk][mt][2] = Qs[rr][kb+4];
            qf[kk][mt][3] = Qs[rr+8][kb+4];
        }
    }

    float m_a[2], m_b[2], l_a[2], l_b[2];
    float O[2][8][4];
    #pragma unroll
    for (int mt = 0; mt < 2; mt++) {
        m_a[mt] = -INFINITY; m_b[mt] = -INFINITY;
        l_a[mt] = 0.f; l_b[mt] = 0.f;
        #pragma unroll
        for (int dt = 0; dt < 8; dt++)
            #pragma unroll
            for (int e = 0; e < 4; e++) O[mt][dt][e] = 0.f;
    }

    for (int kt = 0; kt < SEQ; kt += KT) {
        // K tile (64x64 halves) direct copy
        #pragma unroll
        for (int it = 0; it < 4; it++) {
            int u  = tid + it*128;
            int r  = u >> 3;
            int cu = u & 7;
            uint4 v = *(const uint4*)&kptr[(size_t)(kt + r)*HD + cu*8];
            *(uint4*)&Ks[r][cu*4] = v;
        }
        // V tile transposed: rows d, key-pairs packed, XOR swizzle
        #pragma unroll
        for (int it = 0; it < 2; it++) {
            int u  = tid + it*128;
            int kp = u >> 3;        // key pair 0..31
            int dq = u & 7;         // d-octet 0..7
            uint4 v0 = *(const uint4*)&vptr[(size_t)(kt + 2*kp)*HD + dq*8];
            uint4 v1 = *(const uint4*)&vptr[(size_t)(kt + 2*kp + 1)*HD + dq*8];
            const ushort* p0 = (const ushort*)&v0;
            const ushort* p1 = (const ushort*)&v1;
            int phys = kp ^ (dq << 2);
            #pragma unroll
            for (int j = 0; j < 8; j++) {
                int row = dq*8 + j;
                Vf[row*PW + phys] = (uint32_t)p0[j] | ((uint32_t)p1[j] << 16);
            }
        }
        __syncthreads();

        // S = Q @ K^T : 4 k16 steps; bf shared across mt
        float S[2][8][4];
        #pragma unroll
        for (int mt = 0; mt < 2; mt++)
            #pragma unroll
            for (int nt = 0; nt < 8; nt++)
                #pragma unroll
                for (int e = 0; e < 4; e++) S[mt][nt][e] = 0.f;

        #pragma unroll
        for (int kk = 0; kk < 4; kk++) {
            int kb = kk*8 + q4;
            uint32_t bf[8][2];
            #pragma unroll
            for (int nt = 0; nt < 8; nt++) {
                bf[nt][0] = Ks[nt*8 + gid][kb];
                bf[nt][1] = Ks[nt*8 + gid][kb+4];
            }
            #pragma unroll
            for (int mt = 0; mt < 2; mt++)
                #pragma unroll
                for (int nt = 0; nt < 8; nt++)
                    mma_f16(S[mt][nt], qf[kk][mt], bf[nt]);
        }

        // online softmax (exp2 domain)
        #pragma unroll
        for (int mt = 0; mt < 2; mt++) {
            float ma = S[mt][0][0], mb = S[mt][0][2];
            #pragma unroll
            for (int nt = 0; nt < 8; nt++) {
                ma = fmaxf(ma, fmaxf(S[mt][nt][0], S[mt][nt][1]));
                mb = fmaxf(mb, fmaxf(S[mt][nt][2], S[mt][nt][3]));
            }
            #pragma unroll
            for (int off = 1; off <= 2; off <<= 1) {
                ma = fmaxf(ma, __shfl_xor_sync(0xffffffffu, ma, off));
                mb = fmaxf(mb, __shfl_xor_sync(0xffffffffu, mb, off));
            }
            float mna = fmaxf(m_a[mt], ma);
            float mnb = fmaxf(m_b[mt], mb);
            float alpha_a = ex2f(m_a[mt] - mna);
            float alpha_b = ex2f(m_b[mt] - mnb);
            float sa = 0.f, sb = 0.f;
            #pragma unroll
            for (int nt = 0; nt < 8; nt++) {
                S[mt][nt][0] = ex2f(S[mt][nt][0] - mna);
                S[mt][nt][1] = ex2f(S[mt][nt][1] - mna);
                S[mt][nt][2] = ex2f(S[mt][nt][2] - mnb);
                S[mt][nt][3] = ex2f(S[mt][nt][3] - mnb);
                sa += S[mt][nt][0] + S[mt][nt][1];
                sb += S[mt][nt][2] + S[mt][nt][3];
            }
            #pragma unroll
            for (int off = 1; off <= 2; off <<= 1) {
                sa += __shfl_xor_sync(0xffffffffu, sa, off);
                sb += __shfl_xor_sync(0xffffffffu, sb, off);
            }
            l_a[mt] = l_a[mt] * alpha_a + sa;
            l_b[mt] = l_b[mt] * alpha_b + sb;
            m_a[mt] = mna; m_b[mt] = mnb;
            #pragma unroll
            for (int dt = 0; dt < 8; dt++) {
                O[mt][dt][0] *= alpha_a; O[mt][dt][1] *= alpha_a;
                O[mt][dt][2] *= alpha_b; O[mt][dt][3] *= alpha_b;
            }
        }

        // stage P as packed half2 words (warp-private rows)
        #pragma unroll
        for (int mt = 0; mt < 2; mt++) {
            int rr = w*32 + mt*16 + gid;
            #pragma unroll
            for (int nt = 0; nt < 8; nt++) {
                int cw = nt*4 + q4;
                Ps[rr][cw]   = f2h2(S[mt][nt][0], S[mt][nt][1]);
                Ps[rr+8][cw] = f2h2(S[mt][nt][2], S[mt][nt][3]);
            }
        }
        __syncwarp();

        // O += P @ V : 4 k16 steps over 64 keys; bf from swizzled V
        #pragma unroll
        for (int kk = 0; kk < 4; kk++) {
            uint32_t af[2][4];
            #pragma unroll
            for (int mt = 0; mt < 2; mt++) {
                int rr = w*32 + mt*16 + gid;
                int kb = kk*8 + q4;
                af[mt][0] = Ps[rr][kb];
                af[mt][1] = Ps[rr+8][kb];
                af[mt][2] = Ps[rr][kb+4];
                af[mt][3] = Ps[rr+8][kb+4];
            }
            uint32_t bf[8][2];
            #pragma unroll
            for (int dt = 0; dt < 8; dt++) {
                int row = dt*8 + gid;
                int p0 = (kk*8 + q4)     ^ (dt << 2);
                int p1 = (kk*8 + q4 + 4) ^ (dt << 2);
                bf[dt][0] = Vf[row*PW + p0];
                bf[dt][1] = Vf[row*PW + p1];
            }
            #pragma unroll
            for (int mt = 0; mt < 2; mt++)
                #pragma unroll
                for (int dt = 0; dt < 8; dt++)
                    mma_f16(O[mt][dt], af[mt], bf[dt]);
        }
        __syncthreads();
    }

    // write normalized output as fp16 (B,S,D) for the final GEMM
    #pragma unroll
    for (int mt = 0; mt < 2; mt++) {
        float inv_a = 1.f / l_a[mt];
        float inv_b = 1.f / l_b[mt];
        int rr = w*32 + mt*16 + gid;
        size_t base_a = ((size_t)b*SEQ + q0 + rr)*DIM + h*HD;
        size_t base_b = ((size_t)b*SEQ + q0 + rr + 8)*DIM + h*HD;
        #pragma unroll
        for (int dt = 0; dt < 8; dt++) {
            int col = dt*8 + 2*q4;
            *(uint32_t*)&g_attn[base_a + col] =
                f2h2(O[mt][dt][0]*inv_a, O[mt][dt][1]*inv_a);
            *(uint32_t*)&g_attn[base_b + col] =
                f2h2(O[mt][dt][2]*inv_b, O[mt][dt][3]*inv_b);
        }
    }
}

// ---------------------------------------------------------------------------
extern "C" void kernel_launch(void* const* d_in, const int* in_sizes, int n_in,
                              void* d_out, int out_size)
{
    const float* x      = (const float*)d_in[0];
    const float* w_qkv  = (const float*)d_in[1];
    const float* b_qkv  = (const float*)d_in[2];
    const float* w_out  = (const float*)d_in[3];
    const float* b_out  = (const float*)d_in[4];
    float* out = (float*)d_out;

    __half* wqkvT_p; cudaGetSymbolAddress((void**)&wqkvT_p, g_wqkvT);
    __half* woutT_p; cudaGetSymbolAddress((void**)&woutT_p, g_woutT);

    // 0) weight transpose + fp16 convert
    wtrans<<<dim3(3*DIM/32, DIM/32), dim3(32,8)>>>(w_qkv, wqkvT_p, DIM, 3*DIM);
    wtrans<<<dim3(DIM/32,   DIM/32), dim3(32,8)>>>(w_out, woutT_p, DIM, DIM);

    // 1) QKV projection + scatter (fp16 mma)
    dim3 g1(3*DIM/128, MTOK/128);
    gemm_qkv<<<g1, 256>>>(x, b_qkv);

    // 2) fused attention (fp16 mma)
    size_t asmem = (size_t)ATT_SMEM_WORDS * sizeof(uint32_t);  // 55296 B
    cudaFuncSetAttribute(attn_kernel,
        cudaFuncAttributeMaxDynamicSharedMemorySize, (int)asmem);
    dim3 g2(SEQ/QT, NH, BATCH);
    attn_kernel<<<g2, 128, asmem>>>();

    // 3) output projection (fp16 mma)
    dim3 g3(DIM/128, MTOK/128);
    gemm_out<<<g3, 256>>>(b_out, out);
}

// round 9
// speedup vs baseline: 2.2549x; 1.0370x over previous
#include <cuda_runtime.h>
#include <cuda_fp16.h>
#include <math.h>
#include <stdint.h>

#define BATCH 4
#define SEQ   2048
#define DIM   1024
#define NH    16
#define HD    64
#define MTOK  (BATCH*SEQ)        // 8192
#define SCALE_LOG2E 0.1803368801111204f   // (1/sqrt(64)) * log2(e)

// Scratch (allocation-free: __device__ globals), all fp16
__device__ __half g_wqkvT[3*DIM*DIM];      // [3072][1024] = w_qkv^T
__device__ __half g_woutT[DIM*DIM];        // [1024][1024] = w_out^T
__device__ __half g_q[BATCH*NH*SEQ*HD];    // (B,H,S,Hd), pre-scaled by log2e/8
__device__ __half g_k[BATCH*NH*SEQ*HD];
__device__ __half g_v[BATCH*NH*SEQ*HD];
__device__ __half g_attn[MTOK*DIM];        // (B*S, D)

// ---------------------------------------------------------------------------
// helpers
// ---------------------------------------------------------------------------
__device__ __forceinline__ uint32_t f2h2(float lo, float hi) {
    __half2 h = __floats2half2_rn(lo, hi);   // lo -> low 16 bits
    return *reinterpret_cast<uint32_t*>(&h);
}

__device__ __forceinline__ float ex2f(float x) {
    float r;
    asm("ex2.approx.f32 %0, %1;" : "=f"(r) : "f"(x));
    return r;
}

__device__ __forceinline__ void mma_f16(float c[4],
                                        const uint32_t a[4],
                                        const uint32_t b[2]) {
    asm volatile(
        "mma.sync.aligned.m16n8k16.row.col.f32.f16.f16.f32 "
        "{%0,%1,%2,%3},{%4,%5,%6,%7},{%8,%9},{%0,%1,%2,%3};"
        : "+f"(c[0]), "+f"(c[1]), "+f"(c[2]), "+f"(c[3])
        : "r"(a[0]), "r"(a[1]), "r"(a[2]), "r"(a[3]),
          "r"(b[0]), "r"(b[1]));
}

// ---------------------------------------------------------------------------
// prep: transpose fp32 weight [K][N] -> fp16 [N][K]
// ---------------------------------------------------------------------------
__global__ void wtrans(const float* __restrict__ src, __half* __restrict__ dst,
                       int K, int N)
{
    __shared__ float sm[32][33];
    int tx = threadIdx.x, ty = threadIdx.y;
    int n0 = blockIdx.x * 32, k0 = blockIdx.y * 32;
    #pragma unroll
    for (int j = 0; j < 32; j += 8)
        sm[ty + j][tx] = src[(size_t)(k0 + ty + j)*N + n0 + tx];
    __syncthreads();
    #pragma unroll
    for (int j = 0; j < 32; j += 8)
        dst[(size_t)(n0 + ty + j)*K + k0 + tx] = __float2half(sm[tx][ty + j]);
}

// ---------------------------------------------------------------------------
// fp16 MMA GEMM (unchanged from round 8): 128x128 block, BK=32 halves,
// 256 threads = 8 warps (2x4), warp tile 64x32. SMEM [row][k-word], pitch 20.
// ---------------------------------------------------------------------------
#define KPW 20
#define NKB (DIM/32)   // 32

__device__ __forceinline__ void comp16(const uint32_t (*As)[KPW],
                                       const uint32_t (*Bs)[KPW],
                                       int wr, int wc, int gid, int q4,
                                       float acc[4][4][4]) {
    #pragma unroll
    for (int st = 0; st < 2; st++) {
        int kb = st*8 + q4;
        uint32_t af[4][4], bf[4][2];
        #pragma unroll
        for (int mt = 0; mt < 4; mt++) {
            int m = wr*64 + mt*16 + gid;
            af[mt][0] = As[m][kb];
            af[mt][1] = As[m+8][kb];
            af[mt][2] = As[m][kb+4];
            af[mt][3] = As[m+8][kb+4];
        }
        #pragma unroll
        for (int nt = 0; nt < 4; nt++) {
            int n = wc*32 + nt*8 + gid;
            bf[nt][0] = Bs[n][kb];
            bf[nt][1] = Bs[n][kb+4];
        }
        #pragma unroll
        for (int mt = 0; mt < 4; mt++)
            #pragma unroll
            for (int nt = 0; nt < 4; nt++)
                mma_f16(acc[mt][nt], af[mt], bf[nt]);
    }
}

__device__ __forceinline__ void sts_a32(uint32_t (*As)[KPW], int r, int h,
                                        const float4* q) {
    uint4 u;
    u.x = f2h2(q[0].x, q[0].y); u.y = f2h2(q[0].z, q[0].w);
    u.z = f2h2(q[1].x, q[1].y); u.w = f2h2(q[1].z, q[1].w);
    *(uint4*)&As[r][8*h] = u;
    u.x = f2h2(q[2].x, q[2].y); u.y = f2h2(q[2].z, q[2].w);
    u.z = f2h2(q[3].x, q[3].y); u.w = f2h2(q[3].z, q[3].w);
    *(uint4*)&As[r][8*h + 4] = u;
}

__device__ __forceinline__ void sts_h16(uint32_t (*S)[KPW], int r, int h,
                                        uint4 u0, uint4 u1) {
    *(uint4*)&S[r][8*h]     = u0;
    *(uint4*)&S[r][8*h + 4] = u1;
}

// ---- qkv GEMM: x(fp32) @ wqkvT(fp16) + bias -> scatter g_q/g_k/g_v (fp16)
__global__ void __launch_bounds__(256) gemm_qkv(
    const float* __restrict__ A, const float* __restrict__ bias)
{
    __shared__ uint32_t As[2][128][KPW];
    __shared__ uint32_t Bs[2][128][KPW];
    int tid = threadIdx.x, lane = tid & 31, wid = tid >> 5;
    int wr = wid >> 2, wc = wid & 3, gid = lane >> 2, q4 = lane & 3;
    int row0 = blockIdx.y * 128, col0 = blockIdx.x * 128;
    int r = tid >> 1, h = tid & 1;

    float acc[4][4][4];
    #pragma unroll
    for (int mt = 0; mt < 4; mt++)
        #pragma unroll
        for (int nt = 0; nt < 4; nt++)
            #pragma unroll
            for (int e = 0; e < 4; e++) acc[mt][nt][e] = 0.f;

    const float* aRow = A + (size_t)(row0 + r)*DIM + 16*h;
    const __half* bRow = g_wqkvT + (size_t)(col0 + r)*DIM + 16*h;

    float4 aq[4]; uint4 b0, b1;
    #pragma unroll
    for (int j = 0; j < 4; j++) aq[j] = *(const float4*)&aRow[4*j];
    b0 = *(const uint4*)&bRow[0];
    b1 = *(const uint4*)&bRow[8];
    sts_a32(As[0], r, h, aq);
    sts_h16(Bs[0], r, h, b0, b1);
    __syncthreads();

    int buf = 0;
    for (int kb = 1; ; kb++) {
        bool more = (kb < NKB);
        if (more) {
            #pragma unroll
            for (int j = 0; j < 4; j++) aq[j] = *(const float4*)&aRow[kb*32 + 4*j];
            b0 = *(const uint4*)&bRow[kb*32];
            b1 = *(const uint4*)&bRow[kb*32 + 8];
        }
        comp16(As[buf], Bs[buf], wr, wc, gid, q4, acc);
        if (!more) break;
        sts_a32(As[buf^1], r, h, aq);
        sts_h16(Bs[buf^1], r, h, b0, b1);
        __syncthreads();
        buf ^= 1;
    }

    // epilogue: +bias, scatter as half2 (cols 2q4,2q4+1 adjacent, even)
    #pragma unroll
    for (int mt = 0; mt < 4; mt++) {
        #pragma unroll
        for (int nt = 0; nt < 4; nt++) {
            int col = col0 + wc*32 + nt*8 + 2*q4;
            float2 bs = *(const float2*)&bias[col];
            int three = col >> 10;
            int rem   = col & 1023;
            int hh    = rem >> 6;
            int hd    = rem & 63;
            float sc = (three == 0) ? SCALE_LOG2E : 1.f;
            __half* dstb = (three == 0) ? g_q : (three == 1) ? g_k : g_v;
            #pragma unroll
            for (int half_i = 0; half_i < 2; half_i++) {
                int row = row0 + wr*64 + mt*16 + gid + half_i*8;
                int b  = row >> 11;
                int s  = row & 2047;
                float v0 = (acc[mt][nt][2*half_i]   + bs.x) * sc;
                float v1 = (acc[mt][nt][2*half_i+1] + bs.y) * sc;
                size_t dst = ((size_t)(b*NH + hh)*SEQ + s)*HD + hd;
                *(uint32_t*)&dstb[dst] = f2h2(v0, v1);
            }
        }
    }
}

// ---- out GEMM: g_attn(fp16) @ woutT(fp16) + bias -> d_out (fp32)
__global__ void __launch_bounds__(256) gemm_out(
    const float* __restrict__ bias, float* __restrict__ C)
{
    __shared__ uint32_t As[2][128][KPW];
    __shared__ uint32_t Bs[2][128][KPW];
    int tid = threadIdx.x, lane = tid & 31, wid = tid >> 5;
    int wr = wid >> 2, wc = wid & 3, gid = lane >> 2, q4 = lane & 3;
    int row0 = blockIdx.y * 128, col0 = blockIdx.x * 128;
    int r = tid >> 1, h = tid & 1;

    float acc[4][4][4];
    #pragma unroll
    for (int mt = 0; mt < 4; mt++)
        #pragma unroll
        for (int nt = 0; nt < 4; nt++)
            #pragma unroll
            for (int e = 0; e < 4; e++) acc[mt][nt][e] = 0.f;

    const __half* aRow = g_attn  + (size_t)(row0 + r)*DIM + 16*h;
    const __half* bRow = g_woutT + (size_t)(col0 + r)*DIM + 16*h;

    uint4 a0, a1, b0, b1;
    a0 = *(const uint4*)&aRow[0]; a1 = *(const uint4*)&aRow[8];
    b0 = *(const uint4*)&bRow[0]; b1 = *(const uint4*)&bRow[8];
    sts_h16(As[0], r, h, a0, a1);
    sts_h16(Bs[0], r, h, b0, b1);
    __syncthreads();

    int buf = 0;
    for (int kb = 1; ; kb++) {
        bool more = (kb < NKB);
        if (more) {
            a0 = *(const uint4*)&aRow[kb*32]; a1 = *(const uint4*)&aRow[kb*32 + 8];
            b0 = *(const uint4*)&bRow[kb*32]; b1 = *(const uint4*)&bRow[kb*32 + 8];
        }
        comp16(As[buf], Bs[buf], wr, wc, gid, q4, acc);
        if (!more) break;
        sts_h16(As[buf^1], r, h, a0, a1);
        sts_h16(Bs[buf^1], r, h, b0, b1);
        __syncthreads();
        buf ^= 1;
    }

    #pragma unroll
    for (int mt = 0; mt < 4; mt++) {
        #pragma unroll
        for (int nt = 0; nt < 4; nt++) {
            int col = col0 + wc*32 + nt*8 + 2*q4;
            float2 bs = *(const float2*)&bias[col];
            #pragma unroll
            for (int half_i = 0; half_i < 2; half_i++) {
                int row = row0 + wr*64 + mt*16 + gid + half_i*8;
                float2 v;
                v.x = acc[mt][nt][2*half_i]   + bs.x;
                v.y = acc[mt][nt][2*half_i+1] + bs.y;
                *(float2*)&C[(size_t)row*DIM + col] = v;
            }
        }
    }
}

// ---------------------------------------------------------------------------
// Fused flash attention, fp16 m16n8k16, register-resident P.
// QT=128, 128 threads = 4 warps, warp owns 32 q-rows (2 m16 tiles).
// The S c-fragment layout coincides with the PV a-fragment layout:
//   af[kk] = {pack(S[2kk][0],S[2kk][1]), pack(S[2kk][2],S[2kk][3]),
//             pack(S[2kk+1][0],S[2kk+1][1]), pack(S[2kk+1][2],S[2kk+1][3])}
// so P never goes through SMEM. Q/K tiles pitch 36; V transposed [d][key]
// with word-XOR swizzle (conflict-free STS and LDS).
// ---------------------------------------------------------------------------
#define QT 128
#define KT 64
#define PW 36
#define ATT_SMEM_WORDS ((QT + KT + KT) * PW)   // 9216 words = 36864 B

__global__ void __launch_bounds__(128, 3) attn_kernel()
{
    extern __shared__ uint32_t smu[];
    uint32_t (*Qs)[PW] = (uint32_t (*)[PW])smu;                // [128 q][32 dw]
    uint32_t (*Ks)[PW] = (uint32_t (*)[PW])(smu + QT*PW);      // [64 key][32 dw]
    uint32_t* Vf       = smu + (QT+KT)*PW;                     // [64 d][32 kw] swz

    int tid  = threadIdx.x;
    int lane = tid & 31;
    int w    = tid >> 5;
    int gid  = lane >> 2;
    int q4   = lane & 3;

    int b  = blockIdx.z;
    int h  = blockIdx.y;
    int q0 = blockIdx.x * QT;

    const __half* qptr = g_q + ((size_t)(b*NH + h)*SEQ)*HD;
    const __half* kptr = g_k + ((size_t)(b*NH + h)*SEQ)*HD;
    const __half* vptr = g_v + ((size_t)(b*NH + h)*SEQ)*HD;

    // load Q tile (128x64 halves) via uint4 copies
    #pragma unroll
    for (int it = 0; it < 8; it++) {
        int u  = tid + it*128;
        int r  = u >> 3;
        int cu = u & 7;
        uint4 v = *(const uint4*)&qptr[(size_t)(q0 + r)*HD + cu*8];
        *(uint4*)&Qs[r][cu*4] = v;
    }
    __syncthreads();

    float m_a[2], m_b[2], l_a[2], l_b[2];
    float O[2][8][4];
    #pragma unroll
    for (int mt = 0; mt < 2; mt++) {
        m_a[mt] = -INFINITY; m_b[mt] = -INFINITY;
        l_a[mt] = 0.f; l_b[mt] = 0.f;
        #pragma unroll
        for (int dt = 0; dt < 8; dt++)
            #pragma unroll
            for (int e = 0; e < 4; e++) O[mt][dt][e] = 0.f;
    }

    for (int kt = 0; kt < SEQ; kt += KT) {
        // K tile (64x64 halves) direct copy
        #pragma unroll
        for (int it = 0; it < 4; it++) {
            int u  = tid + it*128;
            int r  = u >> 3;
            int cu = u & 7;
            uint4 v = *(const uint4*)&kptr[(size_t)(kt + r)*HD + cu*8];
            *(uint4*)&Ks[r][cu*4] = v;
        }
        // V tile transposed: rows d, key-pairs packed, XOR swizzle
        #pragma unroll
        for (int it = 0; it < 2; it++) {
            int u  = tid + it*128;
            int kp = u >> 3;        // key pair 0..31
            int dq = u & 7;         // d-octet 0..7
            uint4 v0 = *(const uint4*)&vptr[(size_t)(kt + 2*kp)*HD + dq*8];
            uint4 v1 = *(const uint4*)&vptr[(size_t)(kt + 2*kp + 1)*HD + dq*8];
            const ushort* p0 = (const ushort*)&v0;
            const ushort* p1 = (const ushort*)&v1;
            int phys = kp ^ (dq << 2);
            #pragma unroll
            for (int j = 0; j < 8; j++) {
                int row = dq*8 + j;
                Vf[row*PW + phys] = (uint32_t)p0[j] | ((uint32_t)p1[j] << 16);
            }
        }
        __syncthreads();

        // S = Q @ K^T : 4 k16 steps; qf reloaded from SMEM (no hoist)
        float S[2][8][4];
        #pragma unroll
        for (int mt = 0; mt < 2; mt++)
            #pragma unroll
            for (int nt = 0; nt < 8; nt++)
                #pragma unroll
                for (int e = 0; e < 4; e++) S[mt][nt][e] = 0.f;

        #pragma unroll
        for (int kk = 0; kk < 4; kk++) {
            int kb = kk*8 + q4;
            uint32_t bf[8][2];
            #pragma unroll
            for (int nt = 0; nt < 8; nt++) {
                bf[nt][0] = Ks[nt*8 + gid][kb];
                bf[nt][1] = Ks[nt*8 + gid][kb+4];
            }
            #pragma unroll
            for (int mt = 0; mt < 2; mt++) {
                int rr = w*32 + mt*16 + gid;
                uint32_t qf[4];
                qf[0] = Qs[rr][kb];
                qf[1] = Qs[rr+8][kb];
                qf[2] = Qs[rr][kb+4];
                qf[3] = Qs[rr+8][kb+4];
                #pragma unroll
                for (int nt = 0; nt < 8; nt++)
                    mma_f16(S[mt][nt], qf, bf[nt]);
            }
        }

        // online softmax (exp2 domain)
        #pragma unroll
        for (int mt = 0; mt < 2; mt++) {
            float ma = S[mt][0][0], mb = S[mt][0][2];
            #pragma unroll
            for (int nt = 0; nt < 8; nt++) {
                ma = fmaxf(ma, fmaxf(S[mt][nt][0], S[mt][nt][1]));
                mb = fmaxf(mb, fmaxf(S[mt][nt][2], S[mt][nt][3]));
            }
            #pragma unroll
            for (int off = 1; off <= 2; off <<= 1) {
                ma = fmaxf(ma, __shfl_xor_sync(0xffffffffu, ma, off));
                mb = fmaxf(mb, __shfl_xor_sync(0xffffffffu, mb, off));
            }
            float mna = fmaxf(m_a[mt], ma);
            float mnb = fmaxf(m_b[mt], mb);
            float alpha_a = ex2f(m_a[mt] - mna);
            float alpha_b = ex2f(m_b[mt] - mnb);
            float sa = 0.f, sb = 0.f;
            #pragma unroll
            for (int nt = 0; nt < 8; nt++) {
                S[mt][nt][0] = ex2f(S[mt][nt][0] - mna);
                S[mt][nt][1] = ex2f(S[mt][nt][1] - mna);
                S[mt][nt][2] = ex2f(S[mt][nt][2] - mnb);
                S[mt][nt][3] = ex2f(S[mt][nt][3] - mnb);
                sa += S[mt][nt][0] + S[mt][nt][1];
                sb += S[mt][nt][2] + S[mt][nt][3];
            }
            #pragma unroll
            for (int off = 1; off <= 2; off <<= 1) {
                sa += __shfl_xor_sync(0xffffffffu, sa, off);
                sb += __shfl_xor_sync(0xffffffffu, sb, off);
            }
            l_a[mt] = l_a[mt] * alpha_a + sa;
            l_b[mt] = l_b[mt] * alpha_b + sb;
            m_a[mt] = mna; m_b[mt] = mnb;
            #pragma unroll
            for (int dt = 0; dt < 8; dt++) {
                O[mt][dt][0] *= alpha_a; O[mt][dt][1] *= alpha_a;
                O[mt][dt][2] *= alpha_b; O[mt][dt][3] *= alpha_b;
            }
        }

        // O += P @ V : P stays in registers (S c-frag == PV a-frag layout)
        #pragma unroll
        for (int kk = 0; kk < 4; kk++) {
            uint32_t bf[8][2];
            #pragma unroll
            for (int dt = 0; dt < 8; dt++) {
                int row = dt*8 + gid;
                int p0 = (kk*8 + q4)     ^ (dt << 2);
                int p1 = (kk*8 + q4 + 4) ^ (dt << 2);
                bf[dt][0] = Vf[row*PW + p0];
                bf[dt][1] = Vf[row*PW + p1];
            }
            #pragma unroll
            for (int mt = 0; mt < 2; mt++) {
                uint32_t af[4];
                af[0] = f2h2(S[mt][2*kk][0],   S[mt][2*kk][1]);
                af[1] = f2h2(S[mt][2*kk][2],   S[mt][2*kk][3]);
                af[2] = f2h2(S[mt][2*kk+1][0], S[mt][2*kk+1][1]);
                af[3] = f2h2(S[mt][2*kk+1][2], S[mt][2*kk+1][3]);
                #pragma unroll
                for (int dt = 0; dt < 8; dt++)
                    mma_f16(O[mt][dt], af, bf[dt]);
            }
        }
        __syncthreads();
    }

    // write normalized output as fp16 (B,S,D) for the final GEMM
    #pragma unroll
    for (int mt = 0; mt < 2; mt++) {
        float inv_a = 1.f / l_a[mt];
        float inv_b = 1.f / l_b[mt];
        int rr = w*32 + mt*16 + gid;
        size_t base_a = ((size_t)b*SEQ + q0 + rr)*DIM + h*HD;
        size_t base_b = ((size_t)b*SEQ + q0 + rr + 8)*DIM + h*HD;
        #pragma unroll
        for (int dt = 0; dt < 8; dt++) {
            int col = dt*8 + 2*q4;
            *(uint32_t*)&g_attn[base_a + col] =
                f2h2(O[mt][dt][0]*inv_a, O[mt][dt][1]*inv_a);
            *(uint32_t*)&g_attn[base_b + col] =
                f2h2(O[mt][dt][2]*inv_b, O[mt][dt][3]*inv_b);
        }
    }
}

// ---------------------------------------------------------------------------
extern "C" void kernel_launch(void* const* d_in, const int* in_sizes, int n_in,
                              void* d_out, int out_size)
{
    const float* x      = (const float*)d_in[0];
    const float* w_qkv  = (const float*)d_in[1];
    const float* b_qkv  = (const float*)d_in[2];
    const float* w_out  = (const float*)d_in[3];
    const float* b_out  = (const float*)d_in[4];
    float* out = (float*)d_out;

    __half* wqkvT_p; cudaGetSymbolAddress((void**)&wqkvT_p, g_wqkvT);
    __half* woutT_p; cudaGetSymbolAddress((void**)&woutT_p, g_woutT);

    // 0) weight transpose + fp16 convert
    wtrans<<<dim3(3*DIM/32, DIM/32), dim3(32,8)>>>(w_qkv, wqkvT_p, DIM, 3*DIM);
    wtrans<<<dim3(DIM/32,   DIM/32), dim3(32,8)>>>(w_out, woutT_p, DIM, DIM);

    // 1) QKV projection + scatter (fp16 mma)
    dim3 g1(3*DIM/128, MTOK/128);
    gemm_qkv<<<g1, 256>>>(x, b_qkv);

    // 2) fused attention (fp16 mma, register-resident P)
    size_t asmem = (size_t)ATT_SMEM_WORDS * sizeof(uint32_t);  // 36864 B
    cudaFuncSetAttribute(attn_kernel,
        cudaFuncAttributeMaxDynamicSharedMemorySize, (int)asmem);
    dim3 g2(SEQ/QT, NH, BATCH);
    attn_kernel<<<g2, 128, asmem>>>();

    // 3) output projection (fp16 mma)
    dim3 g3(DIM/128, MTOK/128);
    gemm_out<<<g3, 256>>>(b_out, out);
}

// round 10
// speedup vs baseline: 2.5817x; 1.1449x over previous
#include <cuda_runtime.h>
#include <cuda_fp16.h>
#include <math.h>
#include <stdint.h>

#define BATCH 4
#define SEQ   2048
#define DIM   1024
#define NH    16
#define HD    64
#define MTOK  (BATCH*SEQ)        // 8192
#define SCALE_LOG2E 0.1803368801111204f   // (1/sqrt(64)) * log2(e)

// Scratch (allocation-free: __device__ globals), all fp16
__device__ __half g_wqkvT[3*DIM*DIM];      // [3072][1024] = w_qkv^T
__device__ __half g_woutT[DIM*DIM];        // [1024][1024] = w_out^T
__device__ __half g_q[BATCH*NH*SEQ*HD];    // (B,H,S,Hd), pre-scaled by log2e/8
__device__ __half g_k[BATCH*NH*SEQ*HD];
__device__ __half g_v[BATCH*NH*SEQ*HD];
__device__ __half g_attn[MTOK*DIM];        // (B*S, D)

// ---------------------------------------------------------------------------
// helpers
// ---------------------------------------------------------------------------
__device__ __forceinline__ uint32_t f2h2(float lo, float hi) {
    __half2 h = __floats2half2_rn(lo, hi);
    return *reinterpret_cast<uint32_t*>(&h);
}

__device__ __forceinline__ float ex2f(float x) {
    float r;
    asm("ex2.approx.f32 %0, %1;" : "=f"(r) : "f"(x));
    return r;
}

__device__ __forceinline__ uint32_t smem_u32(const void* p) {
    uint32_t a;
    asm("{ .reg .u64 t; cvta.to.shared.u64 t, %1; cvt.u32.u64 %0, t; }"
        : "=r"(a) : "l"(p));
    return a;
}

__device__ __forceinline__ void mma_f16(float c[4],
                                        const uint32_t a[4],
                                        const uint32_t b[2]) {
    asm volatile(
        "mma.sync.aligned.m16n8k16.row.col.f32.f16.f16.f32 "
        "{%0,%1,%2,%3},{%4,%5,%6,%7},{%8,%9},{%0,%1,%2,%3};"
        : "+f"(c[0]), "+f"(c[1]), "+f"(c[2]), "+f"(c[3])
        : "r"(a[0]), "r"(a[1]), "r"(a[2]), "r"(a[3]),
          "r"(b[0]), "r"(b[1]));
}

#define LDSM4(r0, r1, r2, r3, addr) \
    asm volatile("ldmatrix.sync.aligned.m8n8.x4.shared.b16 {%0,%1,%2,%3},[%4];" \
        : "=r"(r0), "=r"(r1), "=r"(r2), "=r"(r3) : "r"(addr))

#define LDSM4T(r0, r1, r2, r3, addr) \
    asm volatile("ldmatrix.sync.aligned.m8n8.x4.trans.shared.b16 {%0,%1,%2,%3},[%4];" \
        : "=r"(r0), "=r"(r1), "=r"(r2), "=r"(r3) : "r"(addr))

// ---------------------------------------------------------------------------
// prep: transpose fp32 weight [K][N] -> fp16 [N][K]
// ---------------------------------------------------------------------------
__global__ void wtrans(const float* __restrict__ src, __half* __restrict__ dst,
                       int K, int N)
{
    __shared__ float sm[32][33];
    int tx = threadIdx.x, ty = threadIdx.y;
    int n0 = blockIdx.x * 32, k0 = blockIdx.y * 32;
    #pragma unroll
    for (int j = 0; j < 32; j += 8)
        sm[ty + j][tx] = src[(size_t)(k0 + ty + j)*N + n0 + tx];
    __syncthreads();
    #pragma unroll
    for (int j = 0; j < 32; j += 8)
        dst[(size_t)(n0 + ty + j)*K + k0 + tx] = __float2half(sm[tx][ty + j]);
}

// ---------------------------------------------------------------------------
// fp16 MMA GEMM with ldmatrix fragment loads. 128x128 block, BK=32 halves,
// 256 threads = 8 warps (2x4), warp tile 64x32. SMEM [row][k-word], pitch 20
// (LDSM 8-row x 16B wavefronts cover all 32 banks -> conflict-free).
// ---------------------------------------------------------------------------
#define KPW 20
#define NKB (DIM/32)   // 32

// Aln/Bln: per-lane ldmatrix base addresses (include buffer offset).
__device__ __forceinline__ void comp16(uint32_t Aln, uint32_t Bln,
                                       float acc[4][4][4]) {
    #pragma unroll
    for (int st = 0; st < 2; st++) {
        uint32_t af[4][4], bf[4][2];
        #pragma unroll
        for (int mt = 0; mt < 4; mt++)
            LDSM4(af[mt][0], af[mt][1], af[mt][2], af[mt][3],
                  Aln + (mt*16*KPW + st*8)*4);
        #pragma unroll
        for (int ntp = 0; ntp < 2; ntp++)
            LDSM4(bf[2*ntp][0], bf[2*ntp][1], bf[2*ntp+1][0], bf[2*ntp+1][1],
                  Bln + (ntp*16*KPW + st*8)*4);
        #pragma unroll
        for (int mt = 0; mt < 4; mt++)
            #pragma unroll
            for (int nt = 0; nt < 4; nt++)
                mma_f16(acc[mt][nt], af[mt], bf[nt]);
    }
}

__device__ __forceinline__ void sts_a32(uint32_t (*As)[KPW], int r, int h,
                                        const float4* q) {
    uint4 u;
    u.x = f2h2(q[0].x, q[0].y); u.y = f2h2(q[0].z, q[0].w);
    u.z = f2h2(q[1].x, q[1].y); u.w = f2h2(q[1].z, q[1].w);
    *(uint4*)&As[r][8*h] = u;
    u.x = f2h2(q[2].x, q[2].y); u.y = f2h2(q[2].z, q[2].w);
    u.z = f2h2(q[3].x, q[3].y); u.w = f2h2(q[3].z, q[3].w);
    *(uint4*)&As[r][8*h + 4] = u;
}

__device__ __forceinline__ void sts_h16(uint32_t (*S)[KPW], int r, int h,
                                        uint4 u0, uint4 u1) {
    *(uint4*)&S[r][8*h]     = u0;
    *(uint4*)&S[r][8*h + 4] = u1;
}

// ---- qkv GEMM: x(fp32) @ wqkvT(fp16) + bias -> scatter g_q/g_k/g_v (fp16)
__global__ void __launch_bounds__(256) gemm_qkv(
    const float* __restrict__ A, const float* __restrict__ bias)
{
    __shared__ uint32_t As[2][128][KPW];
    __shared__ uint32_t Bs[2][128][KPW];
    int tid = threadIdx.x, lane = tid & 31, wid = tid >> 5;
    int wr = wid >> 2, wc = wid & 3, gid = lane >> 2, q4 = lane & 3;
    int row0 = blockIdx.y * 128, col0 = blockIdx.x * 128;
    int r = tid >> 1, h = tid & 1;
    int mid = lane >> 3, l7 = lane & 7;

    // per-lane ldmatrix bases
    const uint32_t bufw = 128*KPW*4;
    uint32_t Aln0 = smem_u32(As) + (((wr*64 + (mid&1)*8 + l7)*KPW) + (mid>>1)*4)*4;
    uint32_t Bln0 = smem_u32(Bs) + (((wc*32 + (mid>>1)*8 + l7)*KPW) + (mid&1)*4)*4;

    float acc[4][4][4];
    #pragma unroll
    for (int mt = 0; mt < 4; mt++)
        #pragma unroll
        for (int nt = 0; nt < 4; nt++)
            #pragma unroll
            for (int e = 0; e < 4; e++) acc[mt][nt][e] = 0.f;

    const float* aRow = A + (size_t)(row0 + r)*DIM + 16*h;
    const __half* bRow = g_wqkvT + (size_t)(col0 + r)*DIM + 16*h;

    float4 aq[4]; uint4 b0, b1;
    #pragma unroll
    for (int j = 0; j < 4; j++) aq[j] = *(const float4*)&aRow[4*j];
    b0 = *(const uint4*)&bRow[0];
    b1 = *(const uint4*)&bRow[8];
    sts_a32(As[0], r, h, aq);
    sts_h16(Bs[0], r, h, b0, b1);
    __syncthreads();

    int buf = 0;
    for (int kb = 1; ; kb++) {
        bool more = (kb < NKB);
        if (more) {
            #pragma unroll
            for (int j = 0; j < 4; j++) aq[j] = *(const float4*)&aRow[kb*32 + 4*j];
            b0 = *(const uint4*)&bRow[kb*32];
            b1 = *(const uint4*)&bRow[kb*32 + 8];
        }
        comp16(Aln0 + buf*bufw, Bln0 + buf*bufw, acc);
        if (!more) break;
        sts_a32(As[buf^1], r, h, aq);
        sts_h16(Bs[buf^1], r, h, b0, b1);
        __syncthreads();
        buf ^= 1;
    }

    // epilogue: +bias, scatter as half2
    #pragma unroll
    for (int mt = 0; mt < 4; mt++) {
        #pragma unroll
        for (int nt = 0; nt < 4; nt++) {
            int col = col0 + wc*32 + nt*8 + 2*q4;
            float2 bs = *(const float2*)&bias[col];
            int three = col >> 10;
            int rem   = col & 1023;
            int hh    = rem >> 6;
            int hd    = rem & 63;
            float sc = (three == 0) ? SCALE_LOG2E : 1.f;
            __half* dstb = (three == 0) ? g_q : (three == 1) ? g_k : g_v;
            #pragma unroll
            for (int half_i = 0; half_i < 2; half_i++) {
                int row = row0 + wr*64 + mt*16 + gid + half_i*8;
                int b  = row >> 11;
                int s  = row & 2047;
                float v0 = (acc[mt][nt][2*half_i]   + bs.x) * sc;
                float v1 = (acc[mt][nt][2*half_i+1] + bs.y) * sc;
                size_t dst = ((size_t)(b*NH + hh)*SEQ + s)*HD + hd;
                *(uint32_t*)&dstb[dst] = f2h2(v0, v1);
            }
        }
    }
}

// ---- out GEMM: g_attn(fp16) @ woutT(fp16) + bias -> d_out (fp32)
__global__ void __launch_bounds__(256) gemm_out(
    const float* __restrict__ bias, float* __restrict__ C)
{
    __shared__ uint32_t As[2][128][KPW];
    __shared__ uint32_t Bs[2][128][KPW];
    int tid = threadIdx.x, lane = tid & 31, wid = tid >> 5;
    int wr = wid >> 2, wc = wid & 3, gid = lane >> 2, q4 = lane & 3;
    int row0 = blockIdx.y * 128, col0 = blockIdx.x * 128;
    int r = tid >> 1, h = tid & 1;
    int mid = lane >> 3, l7 = lane & 7;

    const uint32_t bufw = 128*KPW*4;
    uint32_t Aln0 = smem_u32(As) + (((wr*64 + (mid&1)*8 + l7)*KPW) + (mid>>1)*4)*4;
    uint32_t Bln0 = smem_u32(Bs) + (((wc*32 + (mid>>1)*8 + l7)*KPW) + (mid&1)*4)*4;

    float acc[4][4][4];
    #pragma unroll
    for (int mt = 0; mt < 4; mt++)
        #pragma unroll
        for (int nt = 0; nt < 4; nt++)
            #pragma unroll
            for (int e = 0; e < 4; e++) acc[mt][nt][e] = 0.f;

    const __half* aRow = g_attn  + (size_t)(row0 + r)*DIM + 16*h;
    const __half* bRow = g_woutT + (size_t)(col0 + r)*DIM + 16*h;

    uint4 a0, a1, b0, b1;
    a0 = *(const uint4*)&aRow[0]; a1 = *(const uint4*)&aRow[8];
    b0 = *(const uint4*)&bRow[0]; b1 = *(const uint4*)&bRow[8];
    sts_h16(As[0], r, h, a0, a1);
    sts_h16(Bs[0], r, h, b0, b1);
    __syncthreads();

    int buf = 0;
    for (int kb = 1; ; kb++) {
        bool more = (kb < NKB);
        if (more) {
            a0 = *(const uint4*)&aRow[kb*32]; a1 = *(const uint4*)&aRow[kb*32 + 8];
            b0 = *(const uint4*)&bRow[kb*32]; b1 = *(const uint4*)&bRow[kb*32 + 8];
        }
        comp16(Aln0 + buf*bufw, Bln0 + buf*bufw, acc);
        if (!more) break;
        sts_h16(As[buf^1], r, h, a0, a1);
        sts_h16(Bs[buf^1], r, h, b0, b1);
        __syncthreads();
        buf ^= 1;
    }

    #pragma unroll
    for (int mt = 0; mt < 4; mt++) {
        #pragma unroll
        for (int nt = 0; nt < 4; nt++) {
            int col = col0 + wc*32 + nt*8 + 2*q4;
            float2 bs = *(const float2*)&bias[col];
            #pragma unroll
            for (int half_i = 0; half_i < 2; half_i++) {
                int row = row0 + wr*64 + mt*16 + gid + half_i*8;
                float2 v;
                v.x = acc[mt][nt][2*half_i]   + bs.x;
                v.y = acc[mt][nt][2*half_i+1] + bs.y;
                *(float2*)&C[(size_t)row*DIM + col] = v;
            }
        }
    }
}

// ---------------------------------------------------------------------------
// Fused flash attention: fp16 m16n8k16, register-resident P, ldmatrix loads.
// QT=128, 128 threads = 4 warps, warp owns 32 q-rows (2 m16 tiles).
// Q [128 q][32 w], K [64 key][32 w], V [64 key][32 w] all row-major pitch 36;
// PV b-fragments come from ldmatrix.x4.trans on row-major V (no transpose
// staging, no swizzle math). LDSM wavefronts conflict-free at pitch 36.
// ---------------------------------------------------------------------------
#define QT 128
#define KT 64
#define PW 36
#define ATT_SMEM_WORDS ((QT + KT + KT) * PW)   // 9216 words = 36864 B

__global__ void __launch_bounds__(128, 3) attn_kernel()
{
    extern __shared__ uint32_t smu[];
    uint32_t (*Qs)[PW] = (uint32_t (*)[PW])smu;                // [128 q][32 dw]
    uint32_t (*Ks)[PW] = (uint32_t (*)[PW])(smu + QT*PW);      // [64 key][32 dw]
    uint32_t (*Vs)[PW] = (uint32_t (*)[PW])(smu + (QT+KT)*PW); // [64 key][32 dw]

    int tid  = threadIdx.x;
    int lane = tid & 31;
    int w    = tid >> 5;
    int mid  = lane >> 3, l7 = lane & 7;

    int b  = blockIdx.z;
    int h  = blockIdx.y;
    int q0 = blockIdx.x * QT;

    const __half* qptr = g_q + ((size_t)(b*NH + h)*SEQ)*HD;
    const __half* kptr = g_k + ((size_t)(b*NH + h)*SEQ)*HD;
    const __half* vptr = g_v + ((size_t)(b*NH + h)*SEQ)*HD;

    // per-lane ldmatrix bases
    uint32_t Qln = smem_u32(Qs) + (((w*32 + (mid&1)*8 + l7)*PW) + (mid>>1)*4)*4;
    uint32_t Kln = smem_u32(Ks) + ((((mid>>1)*8 + l7)*PW) + (mid&1)*4)*4;
    uint32_t Vln = smem_u32(Vs) + ((((mid&1)*8 + l7)*PW) + (mid>>1)*4)*4;

    // load Q tile (128x64 halves) via uint4 copies
    #pragma unroll
    for (int it = 0; it < 8; it++) {
        int u  = tid + it*128;
        int r  = u >> 3;
        int cu = u & 7;
        uint4 v = *(const uint4*)&qptr[(size_t)(q0 + r)*HD + cu*8];
        *(uint4*)&Qs[r][cu*4] = v;
    }
    __syncthreads();

    float m_a[2], m_b[2], l_a[2], l_b[2];
    float O[2][8][4];
    #pragma unroll
    for (int mt = 0; mt < 2; mt++) {
        m_a[mt] = -INFINITY; m_b[mt] = -INFINITY;
        l_a[mt] = 0.f; l_b[mt] = 0.f;
        #pragma unroll
        for (int dt = 0; dt < 8; dt++)
            #pragma unroll
            for (int e = 0; e < 4; e++) O[mt][dt][e] = 0.f;
    }

    for (int kt = 0; kt < SEQ; kt += KT) {
        // K and V tiles (64x64 halves each), direct row-major copies
        #pragma unroll
        for (int it = 0; it < 4; it++) {
            int u  = tid + it*128;
            int r  = u >> 3;
            int cu = u & 7;
            uint4 kv = *(const uint4*)&kptr[(size_t)(kt + r)*HD + cu*8];
            *(uint4*)&Ks[r][cu*4] = kv;
            uint4 vv = *(const uint4*)&vptr[(size_t)(kt + r)*HD + cu*8];
            *(uint4*)&Vs[r][cu*4] = vv;
        }
        __syncthreads();

        // S = Q @ K^T : 4 k16 steps, ldmatrix fragments
        float S[2][8][4];
        #pragma unroll
        for (int mt = 0; mt < 2; mt++)
            #pragma unroll
            for (int nt = 0; nt < 8; nt++)
                #pragma unroll
                for (int e = 0; e < 4; e++) S[mt][nt][e] = 0.f;

        #pragma unroll
        for (int kk = 0; kk < 4; kk++) {
            uint32_t bf[8][2];
            #pragma unroll
            for (int ntp = 0; ntp < 4; ntp++)
                LDSM4(bf[2*ntp][0], bf[2*ntp][1], bf[2*ntp+1][0], bf[2*ntp+1][1],
                      Kln + (ntp*16*PW + kk*8)*4);
            #pragma unroll
            for (int mt = 0; mt < 2; mt++) {
                uint32_t qf[4];
                LDSM4(qf[0], qf[1], qf[2], qf[3],
                      Qln + (mt*16*PW + kk*8)*4);
                #pragma unroll
                for (int nt = 0; nt < 8; nt++)
                    mma_f16(S[mt][nt], qf, bf[nt]);
            }
        }

        // online softmax (exp2 domain)
        #pragma unroll
        for (int mt = 0; mt < 2; mt++) {
            float ma = S[mt][0][0], mb = S[mt][0][2];
            #pragma unroll
            for (int nt = 0; nt < 8; nt++) {
                ma = fmaxf(ma, fmaxf(S[mt][nt][0], S[mt][nt][1]));
                mb = fmaxf(mb, fmaxf(S[mt][nt][2], S[mt][nt][3]));
            }
            #pragma unroll
            for (int off = 1; off <= 2; off <<= 1) {
                ma = fmaxf(ma, __shfl_xor_sync(0xffffffffu, ma, off));
                mb = fmaxf(mb, __shfl_xor_sync(0xffffffffu, mb, off));
            }
            float mna = fmaxf(m_a[mt], ma);
            float mnb = fmaxf(m_b[mt], mb);
            float alpha_a = ex2f(m_a[mt] - mna);
            float alpha_b = ex2f(m_b[mt] - mnb);
            float sa = 0.f, sb = 0.f;
            #pragma unroll
            for (int nt = 0; nt < 8; nt++) {
                S[mt][nt][0] = ex2f(S[mt][nt][0] - mna);
                S[mt][nt][1] = ex2f(S[mt][nt][1] - mna);
                S[mt][nt][2] = ex2f(S[mt][nt][2] - mnb);
                S[mt][nt][3] = ex2f(S[mt][nt][3] - mnb);
                sa += S[mt][nt][0] + S[mt][nt][1];
                sb += S[mt][nt][2] + S[mt][nt][3];
            }
            #pragma unroll
            for (int off = 1; off <= 2; off <<= 1) {
                sa += __shfl_xor_sync(0xffffffffu, sa, off);
                sb += __shfl_xor_sync(0xffffffffu, sb, off);
            }
            l_a[mt] = l_a[mt] * alpha_a + sa;
            l_b[mt] = l_b[mt] * alpha_b + sb;
            m_a[mt] = mna; m_b[mt] = mnb;
            #pragma unroll
            for (int dt = 0; dt < 8; dt++) {
                O[mt][dt][0] *= alpha_a; O[mt][dt][1] *= alpha_a;
                O[mt][dt][2] *= alpha_b; O[mt][dt][3] *= alpha_b;
            }
        }

        // O += P @ V : P in registers; V b-fragments via ldmatrix.trans
        #pragma unroll
        for (int kk = 0; kk < 4; kk++) {
            uint32_t bv[8][2];
            #pragma unroll
            for (int dtp = 0; dtp < 4; dtp++)
                LDSM4T(bv[2*dtp][0], bv[2*dtp][1], bv[2*dtp+1][0], bv[2*dtp+1][1],
                       Vln + (kk*16*PW + dtp*8)*4);
            #pragma unroll
            for (int mt = 0; mt < 2; mt++) {
                uint32_t af[4];
                af[0] = f2h2(S[mt][2*kk][0],   S[mt][2*kk][1]);
                af[1] = f2h2(S[mt][2*kk][2],   S[mt][2*kk][3]);
                af[2] = f2h2(S[mt][2*kk+1][0], S[mt][2*kk+1][1]);
                af[3] = f2h2(S[mt][2*kk+1][2], S[mt][2*kk+1][3]);
                #pragma unroll
                for (int dt = 0; dt < 8; dt++)
                    mma_f16(O[mt][dt], af, bv[dt]);
            }
        }
        __syncthreads();
    }

    // write normalized output as fp16 (B,S,D) for the final GEMM
    int gid = lane >> 2, q4 = lane & 3;
    #pragma unroll
    for (int mt = 0; mt < 2; mt++) {
        float inv_a = 1.f / l_a[mt];
        float inv_b = 1.f / l_b[mt];
        int rr = w*32 + mt*16 + gid;
        size_t base_a = ((size_t)b*SEQ + q0 + rr)*DIM + h*HD;
        size_t base_b = ((size_t)b*SEQ + q0 + rr + 8)*DIM + h*HD;
        #pragma unroll
        for (int dt = 0; dt < 8; dt++) {
            int col = dt*8 + 2*q4;
            *(uint32_t*)&g_attn[base_a + col] =
                f2h2(O[mt][dt][0]*inv_a, O[mt][dt][1]*inv_a);
            *(uint32_t*)&g_attn[base_b + col] =
                f2h2(O[mt][dt][2]*inv_b, O[mt][dt][3]*inv_b);
        }
    }
}

// ---------------------------------------------------------------------------
extern "C" void kernel_launch(void* const* d_in, const int* in_sizes, int n_in,
                              void* d_out, int out_size)
{
    const float* x      = (const float*)d_in[0];
    const float* w_qkv  = (const float*)d_in[1];
    const float* b_qkv  = (const float*)d_in[2];
    const float* w_out  = (const float*)d_in[3];
    const float* b_out  = (const float*)d_in[4];
    float* out = (float*)d_out;

    __half* wqkvT_p; cudaGetSymbolAddress((void**)&wqkvT_p, g_wqkvT);
    __half* woutT_p; cudaGetSymbolAddress((void**)&woutT_p, g_woutT);

    // 0) weight transpose + fp16 convert
    wtrans<<<dim3(3*DIM/32, DIM/32), dim3(32,8)>>>(w_qkv, wqkvT_p, DIM, 3*DIM);
    wtrans<<<dim3(DIM/32,   DIM/32), dim3(32,8)>>>(w_out, woutT_p, DIM, DIM);

    // 1) QKV projection + scatter (fp16 mma + ldmatrix)
    dim3 g1(3*DIM/128, MTOK/128);
    gemm_qkv<<<g1, 256>>>(x, b_qkv);

    // 2) fused attention (fp16 mma, register P, ldmatrix)
    size_t asmem = (size_t)ATT_SMEM_WORDS * sizeof(uint32_t);  // 36864 B
    cudaFuncSetAttribute(attn_kernel,
        cudaFuncAttributeMaxDynamicSharedMemorySize, (int)asmem);
    dim3 g2(SEQ/QT, NH, BATCH);
    attn_kernel<<<g2, 128, asmem>>>();

    // 3) output projection (fp16 mma + ldmatrix)
    dim3 g3(DIM/128, MTOK/128);
    gemm_out<<<g3, 256>>>(b_out, out);
}

// round 11
// speedup vs baseline: 3.1026x; 1.2018x over previous
#include <cuda_runtime.h>
#include <cuda_fp16.h>
#include <math.h>
#include <stdint.h>

#define BATCH 4
#define SEQ   2048
#define DIM   1024
#define NH    16
#define HD    64
#define MTOK  (BATCH*SEQ)        // 8192
#define SCALE_LOG2E 0.1803368801111204f   // (1/sqrt(64)) * log2(e)

// Scratch (allocation-free: __device__ globals), all fp16
__device__ __half g_xh[MTOK*DIM];          // fp16 copy of x
__device__ __half g_wqkvT[3*DIM*DIM];      // [3072][1024] = w_qkv^T
__device__ __half g_woutT[DIM*DIM];        // [1024][1024] = w_out^T
__device__ __half g_q[BATCH*NH*SEQ*HD];    // (B,H,S,Hd), pre-scaled by log2e/8
__device__ __half g_k[BATCH*NH*SEQ*HD];
__device__ __half g_v[BATCH*NH*SEQ*HD];
__device__ __half g_attn[MTOK*DIM];        // (B*S, D)

// ---------------------------------------------------------------------------
// helpers
// ---------------------------------------------------------------------------
__device__ __forceinline__ uint32_t f2h2(float lo, float hi) {
    __half2 h = __floats2half2_rn(lo, hi);
    return *reinterpret_cast<uint32_t*>(&h);
}

__device__ __forceinline__ float ex2f(float x) {
    float r;
    asm("ex2.approx.f32 %0, %1;" : "=f"(r) : "f"(x));
    return r;
}

__device__ __forceinline__ uint32_t smem_u32(const void* p) {
    uint32_t a;
    asm("{ .reg .u64 t; cvta.to.shared.u64 t, %1; cvt.u32.u64 %0, t; }"
        : "=r"(a) : "l"(p));
    return a;
}

__device__ __forceinline__ void mma_f16(float c[4],
                                        const uint32_t a[4],
                                        const uint32_t b[2]) {
    asm volatile(
        "mma.sync.aligned.m16n8k16.row.col.f32.f16.f16.f32 "
        "{%0,%1,%2,%3},{%4,%5,%6,%7},{%8,%9},{%0,%1,%2,%3};"
        : "+f"(c[0]), "+f"(c[1]), "+f"(c[2]), "+f"(c[3])
        : "r"(a[0]), "r"(a[1]), "r"(a[2]), "r"(a[3]),
          "r"(b[0]), "r"(b[1]));
}

#define LDSM4(r0, r1, r2, r3, addr) \
    asm volatile("ldmatrix.sync.aligned.m8n8.x4.shared.b16 {%0,%1,%2,%3},[%4];" \
        : "=r"(r0), "=r"(r1), "=r"(r2), "=r"(r3) : "r"(addr))

#define LDSM4T(r0, r1, r2, r3, addr) \
    asm volatile("ldmatrix.sync.aligned.m8n8.x4.trans.shared.b16 {%0,%1,%2,%3},[%4];" \
        : "=r"(r0), "=r"(r1), "=r"(r2), "=r"(r3) : "r"(addr))

#define CPA16(saddr, gptr) \
    asm volatile("cp.async.cg.shared.global [%0], [%1], 16;" \
        :: "r"(saddr), "l"(gptr) : "memory")
#define CP_COMMIT() asm volatile("cp.async.commit_group;" ::: "memory")
#define CP_WAIT1()  asm volatile("cp.async.wait_group 1;" ::: "memory")
#define CP_WAIT0()  asm volatile("cp.async.wait_group 0;" ::: "memory")

// ---------------------------------------------------------------------------
// prep kernels
// ---------------------------------------------------------------------------
__global__ void xcvt(const float* __restrict__ x, __half* __restrict__ dst)
{
    int i = blockIdx.x * blockDim.x + threadIdx.x;   // over float4s
    float4 v = ((const float4*)x)[i];
    uint2 u;
    u.x = f2h2(v.x, v.y);
    u.y = f2h2(v.z, v.w);
    ((uint2*)dst)[i] = u;
}

__global__ void wtrans(const float* __restrict__ src, __half* __restrict__ dst,
                       int K, int N)
{
    __shared__ float sm[32][33];
    int tx = threadIdx.x, ty = threadIdx.y;
    int n0 = blockIdx.x * 32, k0 = blockIdx.y * 32;
    #pragma unroll
    for (int j = 0; j < 32; j += 8)
        sm[ty + j][tx] = src[(size_t)(k0 + ty + j)*N + n0 + tx];
    __syncthreads();
    #pragma unroll
    for (int j = 0; j < 32; j += 8)
        dst[(size_t)(n0 + ty + j)*K + k0 + tx] = __float2half(sm[tx][ty + j]);
}

// ---------------------------------------------------------------------------
// fp16 MMA GEMM, cp.async double-buffered, ldmatrix fragment loads.
// 128x128 block, BK=32 halves, 256 threads = 8 warps (2x4), warp tile 64x32.
// SMEM [row][k-word], pitch 20 (conflict-free LDSM).
// ---------------------------------------------------------------------------
#define KPW 20
#define NKB (DIM/32)   // 32

__device__ __forceinline__ void comp16(uint32_t Aln, uint32_t Bln,
                                       float acc[4][4][4]) {
    #pragma unroll
    for (int st = 0; st < 2; st++) {
        uint32_t af[4][4], bf[4][2];
        #pragma unroll
        for (int mt = 0; mt < 4; mt++)
            LDSM4(af[mt][0], af[mt][1], af[mt][2], af[mt][3],
                  Aln + (mt*16*KPW + st*8)*4);
        #pragma unroll
        for (int ntp = 0; ntp < 2; ntp++)
            LDSM4(bf[2*ntp][0], bf[2*ntp][1], bf[2*ntp+1][0], bf[2*ntp+1][1],
                  Bln + (ntp*16*KPW + st*8)*4);
        #pragma unroll
        for (int mt = 0; mt < 4; mt++)
            #pragma unroll
            for (int nt = 0; nt < 4; nt++)
                mma_f16(acc[mt][nt], af[mt], bf[nt]);
    }
}

// GEMM mainloop macro: A,B fp16 row-major [.][K=DIM], cp.async pipeline.
#define GEMM_PIPE(aRow, bRow)                                                  \
    uint32_t sA0 = smem_u32(As) + ((r*KPW + 8*h) * 4);                         \
    uint32_t sB0 = smem_u32(Bs) + ((r*KPW + 8*h) * 4);                         \
    CPA16(sA0,      aRow);  CPA16(sA0 + 16, aRow + 8);                         \
    CPA16(sB0,      bRow);  CPA16(sB0 + 16, bRow + 8);                         \
    CP_COMMIT();                                                               \
    int buf = 0;                                                               \
    for (int kb = 0; ; kb++) {                                                 \
        bool more = (kb + 1 < NKB);                                            \
        if (more) {                                                            \
            uint32_t dA = sA0 + (buf^1)*bufb;                                  \
            uint32_t dB = sB0 + (buf^1)*bufb;                                  \
            const __half* ga = aRow + (kb+1)*32;                               \
            const __half* gb = bRow + (kb+1)*32;                               \
            CPA16(dA, ga);  CPA16(dA + 16, ga + 8);                            \
            CPA16(dB, gb);  CPA16(dB + 16, gb + 8);                            \
            CP_COMMIT();                                                       \
            CP_WAIT1();                                                        \
        } else {                                                               \
            CP_WAIT0();                                                        \
        }                                                                      \
        __syncthreads();                                                       \
        comp16(Aln0 + buf*bufb, Bln0 + buf*bufb, acc);                         \
        if (!more) break;                                                      \
        __syncthreads();                                                       \
        buf ^= 1;                                                              \
    }

// ---- qkv GEMM: xh(fp16) @ wqkvT(fp16) + bias -> scatter g_q/g_k/g_v (fp16)
__global__ void __launch_bounds__(256) gemm_qkv(const float* __restrict__ bias)
{
    __shared__ uint32_t As[2][128][KPW];
    __shared__ uint32_t Bs[2][128][KPW];
    int tid = threadIdx.x, lane = tid & 31, wid = tid >> 5;
    int wr = wid >> 2, wc = wid & 3, gid = lane >> 2, q4 = lane & 3;
    int row0 = blockIdx.y * 128, col0 = blockIdx.x * 128;
    int r = tid >> 1, h = tid & 1;
    int mid = lane >> 3, l7 = lane & 7;

    const uint32_t bufb = 128*KPW*4;
    uint32_t Aln0 = smem_u32(As) + (((wr*64 + (mid&1)*8 + l7)*KPW) + (mid>>1)*4)*4;
    uint32_t Bln0 = smem_u32(Bs) + (((wc*32 + (mid>>1)*8 + l7)*KPW) + (mid&1)*4)*4;

    float acc[4][4][4];
    #pragma unroll
    for (int mt = 0; mt < 4; mt++)
        #pragma unroll
        for (int nt = 0; nt < 4; nt++)
            #pragma unroll
            for (int e = 0; e < 4; e++) acc[mt][nt][e] = 0.f;

    const __half* aRow = g_xh    + (size_t)(row0 + r)*DIM + 16*h;
    const __half* bRow = g_wqkvT + (size_t)(col0 + r)*DIM + 16*h;

    GEMM_PIPE(aRow, bRow)

    // epilogue: +bias, scatter as half2
    #pragma unroll
    for (int mt = 0; mt < 4; mt++) {
        #pragma unroll
        for (int nt = 0; nt < 4; nt++) {
            int col = col0 + wc*32 + nt*8 + 2*q4;
            float2 bs = *(const float2*)&bias[col];
            int three = col >> 10;
            int rem   = col & 1023;
            int hh    = rem >> 6;
            int hd    = rem & 63;
            float sc = (three == 0) ? SCALE_LOG2E : 1.f;
            __half* dstb = (three == 0) ? g_q : (three == 1) ? g_k : g_v;
            #pragma unroll
            for (int half_i = 0; half_i < 2; half_i++) {
                int row = row0 + wr*64 + mt*16 + gid + half_i*8;
                int b  = row >> 11;
                int s  = row & 2047;
                float v0 = (acc[mt][nt][2*half_i]   + bs.x) * sc;
                float v1 = (acc[mt][nt][2*half_i+1] + bs.y) * sc;
                size_t dst = ((size_t)(b*NH + hh)*SEQ + s)*HD + hd;
                *(uint32_t*)&dstb[dst] = f2h2(v0, v1);
            }
        }
    }
}

// ---- out GEMM: g_attn(fp16) @ woutT(fp16) + bias -> d_out (fp32)
__global__ void __launch_bounds__(256) gemm_out(
    const float* __restrict__ bias, float* __restrict__ C)
{
    __shared__ uint32_t As[2][128][KPW];
    __shared__ uint32_t Bs[2][128][KPW];
    int tid = threadIdx.x, lane = tid & 31, wid = tid >> 5;
    int wr = wid >> 2, wc = wid & 3, gid = lane >> 2, q4 = lane & 3;
    int row0 = blockIdx.y * 128, col0 = blockIdx.x * 128;
    int r = tid >> 1, h = tid & 1;
    int mid = lane >> 3, l7 = lane & 7;

    const uint32_t bufb = 128*KPW*4;
    uint32_t Aln0 = smem_u32(As) + (((wr*64 + (mid&1)*8 + l7)*KPW) + (mid>>1)*4)*4;
    uint32_t Bln0 = smem_u32(Bs) + (((wc*32 + (mid>>1)*8 + l7)*KPW) + (mid&1)*4)*4;

    float acc[4][4][4];
    #pragma unroll
    for (int mt = 0; mt < 4; mt++)
        #pragma unroll
        for (int nt = 0; nt < 4; nt++)
            #pragma unroll
            for (int e = 0; e < 4; e++) acc[mt][nt][e] = 0.f;

    const __half* aRow = g_attn  + (size_t)(row0 + r)*DIM + 16*h;
    const __half* bRow = g_woutT + (size_t)(col0 + r)*DIM + 16*h;

    GEMM_PIPE(aRow, bRow)

    #pragma unroll
    for (int mt = 0; mt < 4; mt++) {
        #pragma unroll
        for (int nt = 0; nt < 4; nt++) {
            int col = col0 + wc*32 + nt*8 + 2*q4;
            float2 bs = *(const float2*)&bias[col];
            #pragma unroll
            for (int half_i = 0; half_i < 2; half_i++) {
                int row = row0 + wr*64 + mt*16 + gid + half_i*8;
                float2 v;
                v.x = acc[mt][nt][2*half_i]   + bs.x;
                v.y = acc[mt][nt][2*half_i+1] + bs.y;
                *(float2*)&C[(size_t)row*DIM + col] = v;
            }
        }
    }
}

// ---------------------------------------------------------------------------
// Fused flash attention: fp16 m16n8k16, register-resident P, ldmatrix loads,
// cp.async double-buffered K/V tiles.
// QT=128, 128 threads = 4 warps, warp owns 32 q-rows (2 m16 tiles).
// ---------------------------------------------------------------------------
#define QT 128
#define KT 64
#define PW 36
#define ATT_SMEM_WORDS ((QT + 2*KT + 2*KT) * PW)   // 13824 words = 55296 B

__global__ void __launch_bounds__(128, 3) attn_kernel()
{
    extern __shared__ uint32_t smu[];
    uint32_t (*Qs)[PW] = (uint32_t (*)[PW])smu;                   // [128 q][32 dw]
    uint32_t (*Ks)[KT][PW] = (uint32_t (*)[KT][PW])(smu + QT*PW);        // [2][64][36]
    uint32_t (*Vs)[KT][PW] = (uint32_t (*)[KT][PW])(smu + (QT+2*KT)*PW); // [2][64][36]

    int tid  = threadIdx.x;
    int lane = tid & 31;
    int w    = tid >> 5;
    int mid  = lane >> 3, l7 = lane & 7;

    int b  = blockIdx.z;
    int h  = blockIdx.y;
    int q0 = blockIdx.x * QT;

    const __half* qptr = g_q + ((size_t)(b*NH + h)*SEQ)*HD;
    const __half* kptr = g_k + ((size_t)(b*NH + h)*SEQ)*HD;
    const __half* vptr = g_v + ((size_t)(b*NH + h)*SEQ)*HD;

    // cp.async staging: thread covers rows r=tid>>3(+16...), 16B chunk cu
    int sr = tid >> 3;          // 0..15
    int scu = tid & 7;          // 0..7
    const uint32_t kvbufb = KT*PW*4;
    uint32_t sK0 = smem_u32(Ks) + (sr*PW + scu*4)*4;
    uint32_t sV0 = smem_u32(Vs) + (sr*PW + scu*4)*4;

    // per-lane ldmatrix bases
    uint32_t Qln = smem_u32(Qs) + (((w*32 + (mid&1)*8 + l7)*PW) + (mid>>1)*4)*4;
    uint32_t Kln = smem_u32(Ks) + ((((mid>>1)*8 + l7)*PW) + (mid&1)*4)*4;
    uint32_t Vln = smem_u32(Vs) + ((((mid&1)*8 + l7)*PW) + (mid>>1)*4)*4;

    // load Q tile (128x64 halves) via uint4 copies
    #pragma unroll
    for (int it = 0; it < 8; it++) {
        int u  = tid + it*128;
        int r  = u >> 3;
        int cu = u & 7;
        uint4 v = *(const uint4*)&qptr[(size_t)(q0 + r)*HD + cu*8];
        *(uint4*)&Qs[r][cu*4] = v;
    }

    // prefetch K/V tile 0 into buffer 0
    #pragma unroll
    for (int it = 0; it < 4; it++) {
        int r = sr + it*16;
        CPA16(sK0 + it*16*PW*4, &kptr[(size_t)r*HD + scu*8]);
        CPA16(sV0 + it*16*PW*4, &vptr[(size_t)r*HD + scu*8]);
    }
    CP_COMMIT();

    float m_a[2], m_b[2], l_a[2], l_b[2];
    float O[2][8][4];
    #pragma unroll
    for (int mt = 0; mt < 2; mt++) {
        m_a[mt] = -INFINITY; m_b[mt] = -INFINITY;
        l_a[mt] = 0.f; l_b[mt] = 0.f;
        #pragma unroll
        for (int dt = 0; dt < 8; dt++)
            #pragma unroll
            for (int e = 0; e < 4; e++) O[mt][dt][e] = 0.f;
    }

    int buf = 0;
    for (int kt = 0; ; kt += KT) {
        bool more = (kt + KT < SEQ);
        if (more) {
            // prefetch next tile into buf^1
            #pragma unroll
            for (int it = 0; it < 4; it++) {
                int r = kt + KT + sr + it*16;
                CPA16(sK0 + (buf^1)*kvbufb + it*16*PW*4, &kptr[(size_t)r*HD + scu*8]);
                CPA16(sV0 + (buf^1)*kvbufb + it*16*PW*4, &vptr[(size_t)r*HD + scu*8]);
            }
            CP_COMMIT();
            CP_WAIT1();
        } else {
            CP_WAIT0();
        }
        __syncthreads();

        uint32_t Klb = Kln + buf*kvbufb;
        uint32_t Vlb = Vln + buf*kvbufb;

        // S = Q @ K^T : 4 k16 steps, ldmatrix fragments
        float S[2][8][4];
        #pragma unroll
        for (int mt = 0; mt < 2; mt++)
            #pragma unroll
            for (int nt = 0; nt < 8; nt++)
                #pragma unroll
                for (int e = 0; e < 4; e++) S[mt][nt][e] = 0.f;

        #pragma unroll
        for (int kk = 0; kk < 4; kk++) {
            uint32_t bf[8][2];
            #pragma unroll
            for (int ntp = 0; ntp < 4; ntp++)
                LDSM4(bf[2*ntp][0], bf[2*ntp][1], bf[2*ntp+1][0], bf[2*ntp+1][1],
                      Klb + (ntp*16*PW + kk*8)*4);
            #pragma unroll
            for (int mt = 0; mt < 2; mt++) {
                uint32_t qf[4];
                LDSM4(qf[0], qf[1], qf[2], qf[3],
                      Qln + (mt*16*PW + kk*8)*4);
                #pragma unroll
                for (int nt = 0; nt < 8; nt++)
                    mma_f16(S[mt][nt], qf, bf[nt]);
            }
        }

        // online softmax (exp2 domain)
        #pragma unroll
        for (int mt = 0; mt < 2; mt++) {
            float ma = S[mt][0][0], mb = S[mt][0][2];
            #pragma unroll
            for (int nt = 0; nt < 8; nt++) {
                ma = fmaxf(ma, fmaxf(S[mt][nt][0], S[mt][nt][1]));
                mb = fmaxf(mb, fmaxf(S[mt][nt][2], S[mt][nt][3]));
            }
            #pragma unroll
            for (int off = 1; off <= 2; off <<= 1) {
                ma = fmaxf(ma, __shfl_xor_sync(0xffffffffu, ma, off));
                mb = fmaxf(mb, __shfl_xor_sync(0xffffffffu, mb, off));
            }
            float mna = fmaxf(m_a[mt], ma);
            float mnb = fmaxf(m_b[mt], mb);
            float alpha_a = ex2f(m_a[mt] - mna);
            float alpha_b = ex2f(m_b[mt] - mnb);
            float sa = 0.f, sb = 0.f;
            #pragma unroll
            for (int nt = 0; nt < 8; nt++) {
                S[mt][nt][0] = ex2f(S[mt][nt][0] - mna);
                S[mt][nt][1] = ex2f(S[mt][nt][1] - mna);
                S[mt][nt][2] = ex2f(S[mt][nt][2] - mnb);
                S[mt][nt][3] = ex2f(S[mt][nt][3] - mnb);
                sa += S[mt][nt][0] + S[mt][nt][1];
                sb += S[mt][nt][2] + S[mt][nt][3];
            }
            #pragma unroll
            for (int off = 1; off <= 2; off <<= 1) {
                sa += __shfl_xor_sync(0xffffffffu, sa, off);
                sb += __shfl_xor_sync(0xffffffffu, sb, off);
            }
            l_a[mt] = l_a[mt] * alpha_a + sa;
            l_b[mt] = l_b[mt] * alpha_b + sb;
            m_a[mt] = mna; m_b[mt] = mnb;
            #pragma unroll
            for (int dt = 0; dt < 8; dt++) {
                O[mt][dt][0] *= alpha_a; O[mt][dt][1] *= alpha_a;
                O[mt][dt][2] *= alpha_b; O[mt][dt][3] *= alpha_b;
            }
        }

        // O += P @ V : P in registers; V b-fragments via ldmatrix.trans
        #pragma unroll
        for (int kk = 0; kk < 4; kk++) {
            uint32_t bv[8][2];
            #pragma unroll
            for (int dtp = 0; dtp < 4; dtp++)
                LDSM4T(bv[2*dtp][0], bv[2*dtp][1], bv[2*dtp+1][0], bv[2*dtp+1][1],
                       Vlb + (kk*16*PW + dtp*8)*4);
            #pragma unroll
            for (int mt = 0; mt < 2; mt++) {
                uint32_t af[4];
                af[0] = f2h2(S[mt][2*kk][0],   S[mt][2*kk][1]);
                af[1] = f2h2(S[mt][2*kk][2],   S[mt][2*kk][3]);
                af[2] = f2h2(S[mt][2*kk+1][0], S[mt][2*kk+1][1]);
                af[3] = f2h2(S[mt][2*kk+1][2], S[mt][2*kk+1][3]);
                #pragma unroll
                for (int dt = 0; dt < 8; dt++)
                    mma_f16(O[mt][dt], af, bv[dt]);
            }
        }
        if (!more) break;
        __syncthreads();
        buf ^= 1;
    }

    // write normalized output as fp16 (B,S,D) for the final GEMM
    int gid = lane >> 2, q4 = lane & 3;
    #pragma unroll
    for (int mt = 0; mt < 2; mt++) {
        float inv_a = 1.f / l_a[mt];
        float inv_b = 1.f / l_b[mt];
        int rr = w*32 + mt*16 + gid;
        size_t base_a = ((size_t)b*SEQ + q0 + rr)*DIM + h*HD;
        size_t base_b = ((size_t)b*SEQ + q0 + rr + 8)*DIM + h*HD;
        #pragma unroll
        for (int dt = 0; dt < 8; dt++) {
            int col = dt*8 + 2*q4;
            *(uint32_t*)&g_attn[base_a + col] =
                f2h2(O[mt][dt][0]*inv_a, O[mt][dt][1]*inv_a);
            *(uint32_t*)&g_attn[base_b + col] =
                f2h2(O[mt][dt][2]*inv_b, O[mt][dt][3]*inv_b);
        }
    }
}

// ---------------------------------------------------------------------------
extern "C" void kernel_launch(void* const* d_in, const int* in_sizes, int n_in,
                              void* d_out, int out_size)
{
    const float* x      = (const float*)d_in[0];
    const float* w_qkv  = (const float*)d_in[1];
    const float* b_qkv  = (const float*)d_in[2];
    const float* w_out  = (const float*)d_in[3];
    const float* b_out  = (const float*)d_in[4];
    float* out = (float*)d_out;

    __half* xh_p;    cudaGetSymbolAddress((void**)&xh_p,    g_xh);
    __half* wqkvT_p; cudaGetSymbolAddress((void**)&wqkvT_p, g_wqkvT);
    __half* woutT_p; cudaGetSymbolAddress((void**)&woutT_p, g_woutT);

    // 0) prep: x -> fp16, weight transpose + fp16 convert
    xcvt<<<MTOK*DIM/4/256, 256>>>(x, xh_p);
    wtrans<<<dim3(3*DIM/32, DIM/32), dim3(32,8)>>>(w_qkv, wqkvT_p, DIM, 3*DIM);
    wtrans<<<dim3(DIM/32,   DIM/32), dim3(32,8)>>>(w_out, woutT_p, DIM, DIM);

    // 1) QKV projection + scatter (fp16 mma + ldmatrix + cp.async)
    dim3 g1(3*DIM/128, MTOK/128);
    gemm_qkv<<<g1, 256>>>(b_qkv);

    // 2) fused attention (fp16 mma, register P, ldmatrix, cp.async)
    size_t asmem = (size_t)ATT_SMEM_WORDS * sizeof(uint32_t);  // 55296 B
    cudaFuncSetAttribute(attn_kernel,
        cudaFuncAttributeMaxDynamicSharedMemorySize, (int)asmem);
    dim3 g2(SEQ/QT, NH, BATCH);
    attn_kernel<<<g2, 128, asmem>>>();

    // 3) output projection (fp16 mma + ldmatrix + cp.async)
    dim3 g3(DIM/128, MTOK/128);
    gemm_out<<<g3, 256>>>(b_out, out);
}

// round 12
// speedup vs baseline: 3.5108x; 1.1316x over previous
#include <cuda_runtime.h>
#include <cuda_fp16.h>
#include <math.h>
#include <stdint.h>

#define BATCH 4
#define SEQ   2048
#define DIM   1024
#define NH    16
#define HD    64
#define MTOK  (BATCH*SEQ)        // 8192
#define SCALE_LOG2E 0.1803368801111204f   // (1/sqrt(64)) * log2(e)

// Scratch (allocation-free: __device__ globals), all fp16
__device__ __half g_xh[MTOK*DIM];          // fp16 copy of x
__device__ __half g_wqkvT[3*DIM*DIM];      // [3072][1024] = w_qkv^T
__device__ __half g_woutT[DIM*DIM];        // [1024][1024] = w_out^T
__device__ __half g_q[BATCH*NH*SEQ*HD];    // (B,H,S,Hd), pre-scaled by log2e/8
__device__ __half g_k[BATCH*NH*SEQ*HD];
__device__ __half g_v[BATCH*NH*SEQ*HD];
__device__ __half g_attn[MTOK*DIM];        // (B*S, D)

// ---------------------------------------------------------------------------
// helpers
// ---------------------------------------------------------------------------
__device__ __forceinline__ uint32_t f2h2(float lo, float hi) {
    __half2 h = __floats2half2_rn(lo, hi);
    return *reinterpret_cast<uint32_t*>(&h);
}

__device__ __forceinline__ float ex2f(float x) {
    float r;
    asm("ex2.approx.f32 %0, %1;" : "=f"(r) : "f"(x));
    return r;
}

__device__ __forceinline__ uint32_t smem_u32(const void* p) {
    uint32_t a;
    asm("{ .reg .u64 t; cvta.to.shared.u64 t, %1; cvt.u32.u64 %0, t; }"
        : "=r"(a) : "l"(p));
    return a;
}

__device__ __forceinline__ void mma_f16(float c[4],
                                        const uint32_t a[4],
                                        const uint32_t b[2]) {
    asm volatile(
        "mma.sync.aligned.m16n8k16.row.col.f32.f16.f16.f32 "
        "{%0,%1,%2,%3},{%4,%5,%6,%7},{%8,%9},{%0,%1,%2,%3};"
        : "+f"(c[0]), "+f"(c[1]), "+f"(c[2]), "+f"(c[3])
        : "r"(a[0]), "r"(a[1]), "r"(a[2]), "r"(a[3]),
          "r"(b[0]), "r"(b[1]));
}

#define LDSM4(r0, r1, r2, r3, addr) \
    asm volatile("ldmatrix.sync.aligned.m8n8.x4.shared.b16 {%0,%1,%2,%3},[%4];" \
        : "=r"(r0), "=r"(r1), "=r"(r2), "=r"(r3) : "r"(addr))

#define LDSM4T(r0, r1, r2, r3, addr) \
    asm volatile("ldmatrix.sync.aligned.m8n8.x4.trans.shared.b16 {%0,%1,%2,%3},[%4];" \
        : "=r"(r0), "=r"(r1), "=r"(r2), "=r"(r3) : "r"(addr))

#define CPA16(saddr, gptr) \
    asm volatile("cp.async.cg.shared.global [%0], [%1], 16;" \
        :: "r"(saddr), "l"(gptr) : "memory")
#define CP_COMMIT() asm volatile("cp.async.commit_group;" ::: "memory")
#define CP_WAIT2()  asm volatile("cp.async.wait_group 2;" ::: "memory")
#define CP_WAIT1()  asm volatile("cp.async.wait_group 1;" ::: "memory")
#define CP_WAIT0()  asm volatile("cp.async.wait_group 0;" ::: "memory")

// ---------------------------------------------------------------------------
// prep kernels
// ---------------------------------------------------------------------------
__global__ void xcvt(const float* __restrict__ x, __half* __restrict__ dst)
{
    int i = blockIdx.x * blockDim.x + threadIdx.x;   // over float4s
    float4 v = ((const float4*)x)[i];
    uint2 u;
    u.x = f2h2(v.x, v.y);
    u.y = f2h2(v.z, v.w);
    ((uint2*)dst)[i] = u;
}

__global__ void wtrans(const float* __restrict__ src, __half* __restrict__ dst,
                       int K, int N)
{
    __shared__ float sm[32][33];
    int tx = threadIdx.x, ty = threadIdx.y;
    int n0 = blockIdx.x * 32, k0 = blockIdx.y * 32;
    #pragma unroll
    for (int j = 0; j < 32; j += 8)
        sm[ty + j][tx] = src[(size_t)(k0 + ty + j)*N + n0 + tx];
    __syncthreads();
    #pragma unroll
    for (int j = 0; j < 32; j += 8)
        dst[(size_t)(n0 + ty + j)*K + k0 + tx] = __float2half(sm[tx][ty + j]);
}

// ---------------------------------------------------------------------------
// fp16 MMA GEMM, 4-stage cp.async ring, one __syncthreads per k-step.
// 128x128 block, BK=32 halves, 256 threads = 8 warps (2x4), warp tile 64x32.
// SMEM [row][k-word], pitch 20 (conflict-free LDSM). Dynamic SMEM: 80 KB.
// ---------------------------------------------------------------------------
#define KPW 20
#define NKB (DIM/32)            // 32
#define GSTG 4
#define STGB (128*KPW*4)        // bytes per stage per operand
#define GEMM_SMEM (2*GSTG*STGB) // 81920

__device__ __forceinline__ void comp16(uint32_t Aln, uint32_t Bln,
                                       float acc[4][4][4]) {
    #pragma unroll
    for (int st = 0; st < 2; st++) {
        uint32_t af[4][4], bf[4][2];
        #pragma unroll
        for (int mt = 0; mt < 4; mt++)
            LDSM4(af[mt][0], af[mt][1], af[mt][2], af[mt][3],
                  Aln + (mt*16*KPW + st*8)*4);
        #pragma unroll
        for (int ntp = 0; ntp < 2; ntp++)
            LDSM4(bf[2*ntp][0], bf[2*ntp][1], bf[2*ntp+1][0], bf[2*ntp+1][1],
                  Bln + (ntp*16*KPW + st*8)*4);
        #pragma unroll
        for (int mt = 0; mt < 4; mt++)
            #pragma unroll
            for (int nt = 0; nt < 4; nt++)
                mma_f16(acc[mt][nt], af[mt], bf[nt]);
    }
}

// 4-stage mainloop. Needs: aRow/bRow (per-thread gmem ptrs), r, h, lane ids.
#define GEMM_PIPE(aRow, bRow)                                                  \
    extern __shared__ uint32_t dsm[];                                          \
    uint32_t aBase = smem_u32(dsm);                                            \
    uint32_t bBase = aBase + GSTG*STGB;                                        \
    uint32_t sA0 = aBase + (r*KPW + 8*h)*4;                                    \
    uint32_t sB0 = bBase + (r*KPW + 8*h)*4;                                    \
    uint32_t Aln0 = aBase + (((wr*64 + (mid&1)*8 + l7)*KPW) + (mid>>1)*4)*4;   \
    uint32_t Bln0 = bBase + (((wc*32 + (mid>>1)*8 + l7)*KPW) + (mid&1)*4)*4;   \
    _Pragma("unroll")                                                          \
    for (int s = 0; s < GSTG-1; s++) {                                         \
        const __half* ga = (aRow) + s*32;                                      \
        const __half* gb = (bRow) + s*32;                                      \
        CPA16(sA0 + s*STGB, ga);  CPA16(sA0 + s*STGB + 16, ga + 8);            \
        CPA16(sB0 + s*STGB, gb);  CPA16(sB0 + s*STGB + 16, gb + 8);            \
        CP_COMMIT();                                                           \
    }                                                                          \
    for (int kb = 0; kb < NKB; kb++) {                                         \
        if (kb + 2 < NKB)      CP_WAIT2();                                     \
        else if (kb + 1 < NKB) CP_WAIT1();                                     \
        else                   CP_WAIT0();                                     \
        __syncthreads();                                                       \
        comp16(Aln0 + (kb & 3)*STGB, Bln0 + (kb & 3)*STGB, acc);               \
        int nk = kb + GSTG - 1;                                                \
        if (nk < NKB) {                                                        \
            int sl = nk & 3;                                                   \
            const __half* ga = (aRow) + nk*32;                                 \
            const __half* gb = (bRow) + nk*32;                                 \
            CPA16(sA0 + sl*STGB, ga);  CPA16(sA0 + sl*STGB + 16, ga + 8);      \
            CPA16(sB0 + sl*STGB, gb);  CPA16(sB0 + sl*STGB + 16, gb + 8);      \
            CP_COMMIT();                                                       \
        }                                                                      \
    }

// ---- qkv GEMM: xh(fp16) @ wqkvT(fp16) + bias -> scatter g_q/g_k/g_v (fp16)
__global__ void __launch_bounds__(256) gemm_qkv(const float* __restrict__ bias)
{
    int tid = threadIdx.x, lane = tid & 31, wid = tid >> 5;
    int wr = wid >> 2, wc = wid & 3, gid = lane >> 2, q4 = lane & 3;
    int row0 = blockIdx.y * 128, col0 = blockIdx.x * 128;
    int r = tid >> 1, h = tid & 1;
    int mid = lane >> 3, l7 = lane & 7;

    float acc[4][4][4];
    #pragma unroll
    for (int mt = 0; mt < 4; mt++)
        #pragma unroll
        for (int nt = 0; nt < 4; nt++)
            #pragma unroll
            for (int e = 0; e < 4; e++) acc[mt][nt][e] = 0.f;

    const __half* aRow = g_xh    + (size_t)(row0 + r)*DIM + 16*h;
    const __half* bRow = g_wqkvT + (size_t)(col0 + r)*DIM + 16*h;

    GEMM_PIPE(aRow, bRow)

    // epilogue: +bias, scatter as half2
    #pragma unroll
    for (int mt = 0; mt < 4; mt++) {
        #pragma unroll
        for (int nt = 0; nt < 4; nt++) {
            int col = col0 + wc*32 + nt*8 + 2*q4;
            float2 bs = *(const float2*)&bias[col];
            int three = col >> 10;
            int rem   = col & 1023;
            int hh    = rem >> 6;
            int hd    = rem & 63;
            float sc = (three == 0) ? SCALE_LOG2E : 1.f;
            __half* dstb = (three == 0) ? g_q : (three == 1) ? g_k : g_v;
            #pragma unroll
            for (int half_i = 0; half_i < 2; half_i++) {
                int row = row0 + wr*64 + mt*16 + gid + half_i*8;
                int b  = row >> 11;
                int s  = row & 2047;
                float v0 = (acc[mt][nt][2*half_i]   + bs.x) * sc;
                float v1 = (acc[mt][nt][2*half_i+1] + bs.y) * sc;
                size_t dst = ((size_t)(b*NH + hh)*SEQ + s)*HD + hd;
                *(uint32_t*)&dstb[dst] = f2h2(v0, v1);
            }
        }
    }
}

// ---- out GEMM: g_attn(fp16) @ woutT(fp16) + bias -> d_out (fp32)
__global__ void __launch_bounds__(256) gemm_out(
    const float* __restrict__ bias, float* __restrict__ C)
{
    int tid = threadIdx.x, lane = tid & 31, wid = tid >> 5;
    int wr = wid >> 2, wc = wid & 3, gid = lane >> 2, q4 = lane & 3;
    int row0 = blockIdx.y * 128, col0 = blockIdx.x * 128;
    int r = tid >> 1, h = tid & 1;
    int mid = lane >> 3, l7 = lane & 7;

    float acc[4][4][4];
    #pragma unroll
    for (int mt = 0; mt < 4; mt++)
        #pragma unroll
        for (int nt = 0; nt < 4; nt++)
            #pragma unroll
            for (int e = 0; e < 4; e++) acc[mt][nt][e] = 0.f;

    const __half* aRow = g_attn  + (size_t)(row0 + r)*DIM + 16*h;
    const __half* bRow = g_woutT + (size_t)(col0 + r)*DIM + 16*h;

    GEMM_PIPE(aRow, bRow)

    #pragma unroll
    for (int mt = 0; mt < 4; mt++) {
        #pragma unroll
        for (int nt = 0; nt < 4; nt++) {
            int col = col0 + wc*32 + nt*8 + 2*q4;
            float2 bs = *(const float2*)&bias[col];
            #pragma unroll
            for (int half_i = 0; half_i < 2; half_i++) {
                int row = row0 + wr*64 + mt*16 + gid + half_i*8;
                float2 v;
                v.x = acc[mt][nt][2*half_i]   + bs.x;
                v.y = acc[mt][nt][2*half_i+1] + bs.y;
                *(float2*)&C[(size_t)row*DIM + col] = v;
            }
        }
    }
}

// ---------------------------------------------------------------------------
// Fused flash attention: fp16 m16n8k16, register-resident P, ldmatrix loads,
// 3-stage cp.async ring for K/V tiles.
// QT=128, 128 threads = 4 warps, warp owns 32 q-rows (2 m16 tiles).
// ---------------------------------------------------------------------------
#define QT 128
#define KT 64
#define PW 36
#define ASTG 3
#define KVSTGB (KT*PW*4)
#define ATT_SMEM_WORDS ((QT + 2*ASTG*KT) * PW)   // 18432 words = 73728 B

__global__ void __launch_bounds__(128, 3) attn_kernel()
{
    extern __shared__ uint32_t smu[];
    uint32_t (*Qs)[PW] = (uint32_t (*)[PW])smu;      // [128 q][32 dw]
    uint32_t kBase = smem_u32(smu + QT*PW);          // K: 3 stages
    uint32_t vBase = kBase + ASTG*KVSTGB;            // V: 3 stages

    int tid  = threadIdx.x;
    int lane = tid & 31;
    int w    = tid >> 5;
    int mid  = lane >> 3, l7 = lane & 7;

    int b  = blockIdx.z;
    int h  = blockIdx.y;
    int q0 = blockIdx.x * QT;

    const __half* qptr = g_q + ((size_t)(b*NH + h)*SEQ)*HD;
    const __half* kptr = g_k + ((size_t)(b*NH + h)*SEQ)*HD;
    const __half* vptr = g_v + ((size_t)(b*NH + h)*SEQ)*HD;

    // cp.async staging addresses
    int sr = tid >> 3;          // 0..15
    int scu = tid & 7;          // 0..7
    uint32_t sK0 = kBase + (sr*PW + scu*4)*4;
    uint32_t sV0 = vBase + (sr*PW + scu*4)*4;

    // per-lane ldmatrix bases
    uint32_t Qln = smem_u32(Qs) + (((w*32 + (mid&1)*8 + l7)*PW) + (mid>>1)*4)*4;
    uint32_t Kln = kBase + ((((mid>>1)*8 + l7)*PW) + (mid&1)*4)*4;
    uint32_t Vln = vBase + ((((mid&1)*8 + l7)*PW) + (mid>>1)*4)*4;

    // load Q tile (128x64 halves) via uint4 copies
    #pragma unroll
    for (int it = 0; it < 8; it++) {
        int u  = tid + it*128;
        int r  = u >> 3;
        int cu = u & 7;
        uint4 v = *(const uint4*)&qptr[(size_t)(q0 + r)*HD + cu*8];
        *(uint4*)&Qs[r][cu*4] = v;
    }

    // prefetch K/V tiles 0,1 into stages 0,1
    #pragma unroll
    for (int s = 0; s < ASTG-1; s++) {
        #pragma unroll
        for (int it = 0; it < 4; it++) {
            int r = s*KT + sr + it*16;
            CPA16(sK0 + s*KVSTGB + it*16*PW*4, &kptr[(size_t)r*HD + scu*8]);
            CPA16(sV0 + s*KVSTGB + it*16*PW*4, &vptr[(size_t)r*HD + scu*8]);
        }
        CP_COMMIT();
    }

    float m_a[2], m_b[2], l_a[2], l_b[2];
    float O[2][8][4];
    #pragma unroll
    for (int mt = 0; mt < 2; mt++) {
        m_a[mt] = -INFINITY; m_b[mt] = -INFINITY;
        l_a[mt] = 0.f; l_b[mt] = 0.f;
        #pragma unroll
        for (int dt = 0; dt < 8; dt++)
            #pragma unroll
            for (int e = 0; e < 4; e++) O[mt][dt][e] = 0.f;
    }

    const int NTI = SEQ/KT;   // 32
    for (int ti = 0; ti < NTI; ti++) {
        if (ti + 1 < NTI) CP_WAIT1();
        else              CP_WAIT0();
        __syncthreads();

        int sl = ti % ASTG;
        uint32_t Klb = Kln + sl*KVSTGB;
        uint32_t Vlb = Vln + sl*KVSTGB;

        // S = Q @ K^T : 4 k16 steps, ldmatrix fragments
        float S[2][8][4];
        #pragma unroll
        for (int mt = 0; mt < 2; mt++)
            #pragma unroll
            for (int nt = 0; nt < 8; nt++)
                #pragma unroll
                for (int e = 0; e < 4; e++) S[mt][nt][e] = 0.f;

        #pragma unroll
        for (int kk = 0; kk < 4; kk++) {
            uint32_t bf[8][2];
            #pragma unroll
            for (int ntp = 0; ntp < 4; ntp++)
                LDSM4(bf[2*ntp][0], bf[2*ntp][1], bf[2*ntp+1][0], bf[2*ntp+1][1],
                      Klb + (ntp*16*PW + kk*8)*4);
            #pragma unroll
            for (int mt = 0; mt < 2; mt++) {
                uint32_t qf[4];
                LDSM4(qf[0], qf[1], qf[2], qf[3],
                      Qln + (mt*16*PW + kk*8)*4);
                #pragma unroll
                for (int nt = 0; nt < 8; nt++)
                    mma_f16(S[mt][nt], qf, bf[nt]);
            }
        }

        // prefetch tile ti+2 into stage (ti+2)%3 (overwrites tile ti-1's slot)
        int nt2 = ti + ASTG - 1;
        if (nt2 < NTI) {
            int ps = nt2 % ASTG;
            #pragma unroll
            for (int it = 0; it < 4; it++) {
                int r = nt2*KT + sr + it*16;
                CPA16(sK0 + ps*KVSTGB + it*16*PW*4, &kptr[(size_t)r*HD + scu*8]);
                CPA16(sV0 + ps*KVSTGB + it*16*PW*4, &vptr[(size_t)r*HD + scu*8]);
            }
            CP_COMMIT();
        }

        // online softmax (exp2 domain)
        #pragma unroll
        for (int mt = 0; mt < 2; mt++) {
            float ma = S[mt][0][0], mb = S[mt][0][2];
            #pragma unroll
            for (int nt = 0; nt < 8; nt++) {
                ma = fmaxf(ma, fmaxf(S[mt][nt][0], S[mt][nt][1]));
                mb = fmaxf(mb, fmaxf(S[mt][nt][2], S[mt][nt][3]));
            }
            #pragma unroll
            for (int off = 1; off <= 2; off <<= 1) {
                ma = fmaxf(ma, __shfl_xor_sync(0xffffffffu, ma, off));
                mb = fmaxf(mb, __shfl_xor_sync(0xffffffffu, mb, off));
            }
            float mna = fmaxf(m_a[mt], ma);
            float mnb = fmaxf(m_b[mt], mb);
            float alpha_a = ex2f(m_a[mt] - mna);
            float alpha_b = ex2f(m_b[mt] - mnb);
            float sa = 0.f, sb = 0.f;
            #pragma unroll
            for (int nt = 0; nt < 8; nt++) {
                S[mt][nt][0] = ex2f(S[mt][nt][0] - mna);
                S[mt][nt][1] = ex2f(S[mt][nt][1] - mna);
                S[mt][nt][2] = ex2f(S[mt][nt][2] - mnb);
                S[mt][nt][3] = ex2f(S[mt][nt][3] - mnb);
                sa += S[mt][nt][0] + S[mt][nt][1];
                sb += S[mt][nt][2] + S[mt][nt][3];
            }
            #pragma unroll
            for (int off = 1; off <= 2; off <<= 1) {
                sa += __shfl_xor_sync(0xffffffffu, sa, off);
                sb += __shfl_xor_sync(0xffffffffu, sb, off);
            }
            l_a[mt] = l_a[mt] * alpha_a + sa;
            l_b[mt] = l_b[mt] * alpha_b + sb;
            m_a[mt] = mna; m_b[mt] = mnb;
            #pragma unroll
            for (int dt = 0; dt < 8; dt++) {
                O[mt][dt][0] *= alpha_a; O[mt][dt][1] *= alpha_a;
                O[mt][dt][2] *= alpha_b; O[mt][dt][3] *= alpha_b;
            }
        }

        // O += P @ V : P in registers; V b-fragments via ldmatrix.trans
        #pragma unroll
        for (int kk = 0; kk < 4; kk++) {
            uint32_t bv[8][2];
            #pragma unroll
            for (int dtp = 0; dtp < 4; dtp++)
                LDSM4T(bv[2*dtp][0], bv[2*dtp][1], bv[2*dtp+1][0], bv[2*dtp+1][1],
                       Vlb + (kk*16*PW + dtp*8)*4);
            #pragma unroll
            for (int mt = 0; mt < 2; mt++) {
                uint32_t af[4];
                af[0] = f2h2(S[mt][2*kk][0],   S[mt][2*kk][1]);
                af[1] = f2h2(S[mt][2*kk][2],   S[mt][2*kk][3]);
                af[2] = f2h2(S[mt][2*kk+1][0], S[mt][2*kk+1][1]);
                af[3] = f2h2(S[mt][2*kk+1][2], S[mt][2*kk+1][3]);
                #pragma unroll
                for (int dt = 0; dt < 8; dt++)
                    mma_f16(O[mt][dt], af, bv[dt]);
            }
        }
    }

    // write normalized output as fp16 (B,S,D) for the final GEMM
    int gid = lane >> 2, q4 = lane & 3;
    #pragma unroll
    for (int mt = 0; mt < 2; mt++) {
        float inv_a = 1.f / l_a[mt];
        float inv_b = 1.f / l_b[mt];
        int rr = w*32 + mt*16 + gid;
        size_t base_a = ((size_t)b*SEQ + q0 + rr)*DIM + h*HD;
        size_t base_b = ((size_t)b*SEQ + q0 + rr + 8)*DIM + h*HD;
        #pragma unroll
        for (int dt = 0; dt < 8; dt++) {
            int col = dt*8 + 2*q4;
            *(uint32_t*)&g_attn[base_a + col] =
                f2h2(O[mt][dt][0]*inv_a, O[mt][dt][1]*inv_a);
            *(uint32_t*)&g_attn[base_b + col] =
                f2h2(O[mt][dt][2]*inv_b, O[mt][dt][3]*inv_b);
        }
    }
}

// ---------------------------------------------------------------------------
extern "C" void kernel_launch(void* const* d_in, const int* in_sizes, int n_in,
                              void* d_out, int out_size)
{
    const float* x      = (const float*)d_in[0];
    const float* w_qkv  = (const float*)d_in[1];
    const float* b_qkv  = (const float*)d_in[2];
    const float* w_out  = (const float*)d_in[3];
    const float* b_out  = (const float*)d_in[4];
    float* out = (float*)d_out;

    __half* xh_p;    cudaGetSymbolAddress((void**)&xh_p,    g_xh);
    __half* wqkvT_p; cudaGetSymbolAddress((void**)&wqkvT_p, g_wqkvT);
    __half* woutT_p; cudaGetSymbolAddress((void**)&woutT_p, g_woutT);

    // 0) prep: x -> fp16, weight transpose + fp16 convert
    xcvt<<<MTOK*DIM/4/256, 256>>>(x, xh_p);
    wtrans<<<dim3(3*DIM/32, DIM/32), dim3(32,8)>>>(w_qkv, wqkvT_p, DIM, 3*DIM);
    wtrans<<<dim3(DIM/32,   DIM/32), dim3(32,8)>>>(w_out, woutT_p, DIM, DIM);

    // 1) QKV projection + scatter (4-stage cp.async)
    cudaFuncSetAttribute(gemm_qkv,
        cudaFuncAttributeMaxDynamicSharedMemorySize, GEMM_SMEM);
    dim3 g1(3*DIM/128, MTOK/128);
    gemm_qkv<<<g1, 256, GEMM_SMEM>>>(b_qkv);

    // 2) fused attention (3-stage cp.async)
    size_t asmem = (size_t)ATT_SMEM_WORDS * sizeof(uint32_t);  // 73728 B
    cudaFuncSetAttribute(attn_kernel,
        cudaFuncAttributeMaxDynamicSharedMemorySize, (int)asmem);
    dim3 g2(SEQ/QT, NH, BATCH);
    attn_kernel<<<g2, 128, asmem>>>();

    // 3) output projection (4-stage cp.async)
    cudaFuncSetAttribute(gemm_out,
        cudaFuncAttributeMaxDynamicSharedMemorySize, GEMM_SMEM);
    dim3 g3(DIM/128, MTOK/128);
    gemm_out<<<g3, 256, GEMM_SMEM>>>(b_out, out);
}